// round 3
// baseline (speedup 1.0000x reference)
#include <cuda_runtime.h>
#include <cstdint>

#define IN_F   4096
#define OUT_F  11008
#define TOK    16
#define CHUNK  256
#define NCHUNK (IN_F / CHUNK)       // 16
#define ITPC   (CHUNK / 128)        // 2 warp-iterations per chunk
#define NIT    (IN_F / 128)         // 32 total warp-iterations
#define THREADS 256
#define WARPS  8
#define RPW    4
#define ROWS_PER_CTA (RPW * WARPS)  // 32
#define NCTA   (OUT_F / ROWS_PER_CTA)

// x transposed to [i][16 tokens] as 4 float4 quads per i. 256 KB scratch.
__device__ float4 g_xT[IN_F * 4];

__global__ void transpose_x_kernel(const float* __restrict__ x) {
    int i = blockIdx.x * blockDim.x + threadIdx.x;
    float v[TOK];
#pragma unroll
    for (int t = 0; t < TOK; t++) v[t] = x[t * IN_F + i];
#pragma unroll
    for (int q = 0; q < 4; q++)
        g_xT[i * 4 + q] = make_float4(v[4*q], v[4*q+1], v[4*q+2], v[4*q+3]);
}

typedef unsigned long long u64;
typedef unsigned int       u32;

__device__ __forceinline__ u64 pack2(float lo, float hi) {
    u64 r; asm("mov.b64 %0, {%1, %2};" : "=l"(r) : "f"(lo), "f"(hi)); return r;
}
__device__ __forceinline__ void unpack2(u64 v, float& lo, float& hi) {
    asm("mov.b64 {%0, %1}, %2;" : "=f"(lo), "=f"(hi) : "l"(v));
}
__device__ __forceinline__ void ffma2(u64& d, u64 a, u64 b) {
    asm("fma.rn.f32x2 %0, %1, %2, %0;" : "+l"(d) : "l"(a), "l"(b));
}
__device__ __forceinline__ u64 fadd2(u64 a, u64 b) {
    u64 r; asm("add.rn.f32x2 %0, %1, %2;" : "=l"(r) : "l"(a), "l"(b)); return r;
}
__device__ __forceinline__ void cp_async16(u32 dst, const void* src) {
    asm volatile("cp.async.cg.shared.global [%0], [%1], 16;\n" :: "r"(dst), "l"(src));
}
__device__ __forceinline__ void cp_commit() {
    asm volatile("cp.async.commit_group;\n" ::: "memory");
}

__global__ void __launch_bounds__(THREADS, 2) q4_gemm_kernel(
    const int*   __restrict__ wq,      // [OUT_F][IN_F] int32 nibbles 0..15
    const float* __restrict__ wscale,  // [OUT_F][IN_F/32]
    const float* __restrict__ bias,    // [OUT_F]
    float*       __restrict__ out)     // [TOK][OUT_F]
{
    // x tile: [buf][quad][slot] (u64 pairs so LDS.128 feeds FFMA2 directly). 32 KB.
    __shared__ ulonglong2 xs[2][4][CHUNK];
    __shared__ float res[ROWS_PER_CTA][TOK + 1];

    const int tid  = threadIdx.x;
    const int warp = tid >> 5;
    const int lane = tid & 31;
    const int row0 = blockIdx.x * ROWS_PER_CTA + warp * RPW;

    const u32 xs_base = (u32)__cvta_generic_to_shared(&xs[0][0][0]);
    // per-thread staging slot (element idx == tid within each chunk)
    const int sslot = tid ^ ((tid >> 3) & 7);

    u64 acc[RPW][8];
#pragma unroll
    for (int r = 0; r < RPW; r++)
#pragma unroll
        for (int k = 0; k < 8; k++) acc[r][k] = 0ull;

    // ---- stage chunk 0 into buf 0 ----
    {
        const float4* src = g_xT + (size_t)tid * 4;
#pragma unroll
        for (int q = 0; q < 4; q++)
            cp_async16(xs_base + (u32)(((0*4 + q) * CHUNK + sslot) * 16), src + q);
        cp_commit();
    }

    // ---- prefetch first weight iteration ----
    int4  qn[RPW]; float sn[RPW];
    {
        const int gi = lane * 4;
#pragma unroll
        for (int r = 0; r < RPW; r++) {
            qn[r] = __ldg((const int4*)(wq + (size_t)(row0 + r) * IN_F + gi));
            sn[r] = __ldg(wscale + (size_t)(row0 + r) * (IN_F / 32) + (gi >> 5));
        }
    }

    for (int c = 0; c < NCHUNK; c++) {
        const int buf = c & 1;
        if (c + 1 < NCHUNK) {
            // stage next chunk into the other buffer; its previous readers
            // finished before the last __syncthreads()
            const float4* src = g_xT + (size_t)((c + 1) * CHUNK + tid) * 4;
#pragma unroll
            for (int q = 0; q < 4; q++)
                cp_async16(xs_base + (u32)((((buf ^ 1) * 4 + q) * CHUNK + sslot) * 16),
                           src + q);
            cp_commit();
            asm volatile("cp.async.wait_group 1;\n" ::: "memory");
        } else {
            asm volatile("cp.async.wait_group 0;\n" ::: "memory");
        }
        __syncthreads();   // chunk c visible to all warps

#pragma unroll
        for (int it = 0; it < ITPC; it++) {
            const int itg = c * ITPC + it;

            // consume prefetched weights, then immediately prefetch next
            int4 qc[RPW]; float sc[RPW];
#pragma unroll
            for (int r = 0; r < RPW; r++) { qc[r] = qn[r]; sc[r] = sn[r]; }
            if (itg + 1 < NIT) {
                const int gi = (itg + 1) * 128 + lane * 4;
#pragma unroll
                for (int r = 0; r < RPW; r++) {
                    qn[r] = __ldg((const int4*)(wq + (size_t)(row0 + r) * IN_F + gi));
                    sn[r] = __ldg(wscale + (size_t)(row0 + r) * (IN_F / 32) + (gi >> 5));
                }
            }

            float m[RPW];
#pragma unroll
            for (int r = 0; r < RPW; r++) m[r] = sc[r] * -8.0f;

#pragma unroll
            for (int j = 0; j < 4; j++) {
                const int ii   = it * 128 + lane * 4 + j;
                const int slot = ii ^ ((ii >> 3) & 7);
                const ulonglong2 p0 = xs[buf][0][slot];
                const ulonglong2 p1 = xs[buf][1][slot];
                const ulonglong2 p2 = xs[buf][2][slot];
                const ulonglong2 p3 = xs[buf][3][slot];
#pragma unroll
                for (int r = 0; r < RPW; r++) {
                    const int q = (j == 0) ? qc[r].x : (j == 1) ? qc[r].y
                                : (j == 2) ? qc[r].z : qc[r].w;
                    // exact int->float without I2F: (2^23|q) - 2^23 == q
                    const float qf =
                        __uint_as_float(0x4B000000u | (unsigned)q) - 8388608.0f;
                    const float wf = fmaf(qf, sc[r], m[r]);   // RN((q-8)*s)
                    const u64 wp = pack2(wf, wf);
                    ffma2(acc[r][0], wp, p0.x); ffma2(acc[r][1], wp, p0.y);
                    ffma2(acc[r][2], wp, p1.x); ffma2(acc[r][3], wp, p1.y);
                    ffma2(acc[r][4], wp, p2.x); ffma2(acc[r][5], wp, p2.y);
                    ffma2(acc[r][6], wp, p3.x); ffma2(acc[r][7], wp, p3.y);
                }
            }
        }
        __syncthreads();   // all warps done reading buf before restage
    }

    // ---- butterfly reduction with packed adds, stage to smem ----
#pragma unroll
    for (int r = 0; r < RPW; r++) {
#pragma unroll
        for (int k = 0; k < 8; k++) {
            u64 v = acc[r][k];
#pragma unroll
            for (int off = 16; off > 0; off >>= 1)
                v = fadd2(v, __shfl_xor_sync(0xffffffffu, v, off));
            if (lane == 0) {
                float lo, hi; unpack2(v, lo, hi);
                res[warp * RPW + r][2 * k]     = lo;
                res[warp * RPW + r][2 * k + 1] = hi;
            }
        }
    }
    __syncthreads();

    // ---- coalesced write-out with bias ----
    const int colbase = blockIdx.x * ROWS_PER_CTA;
#pragma unroll
    for (int idx = tid; idx < ROWS_PER_CTA * TOK; idx += THREADS) {
        const int t   = idx >> 5;       // token
        const int row = idx & 31;       // row within CTA
        out[(size_t)t * OUT_F + colbase + row] = res[row][t] + bias[colbase + row];
    }
}

extern "C" void kernel_launch(void* const* d_in, const int* in_sizes, int n_in,
                              void* d_out, int out_size) {
    const float* x      = (const float*)d_in[0];  // [16, 4096]
    const int*   wq     = (const int*)  d_in[1];  // [11008, 4096]
    const float* wscale = (const float*)d_in[2];  // [11008, 128]
    const float* bias   = (const float*)d_in[3];  // [11008]
    float* out = (float*)d_out;                   // [16, 11008]

    transpose_x_kernel<<<IN_F / 256, 256>>>(x);
    q4_gemm_kernel<<<NCTA, THREADS>>>(wq, wscale, bias, out);
}

// round 4
// speedup vs baseline: 1.1664x; 1.1664x over previous
#include <cuda_runtime.h>
#include <cstdint>

#define IN_F   4096
#define OUT_F  11008
#define TOK    16
#define CHUNK  512
#define NCHUNK (IN_F / CHUNK)       // 8
#define ITPC   (CHUNK / 128)        // 4 warp-iterations per chunk
#define NIT    (IN_F / 128)         // 32 total warp-iterations
#define THREADS 256
#define WARPS  8
#define RPW    4
#define ROWS_PER_CTA (RPW * WARPS)  // 32
#define NCTA   (OUT_F / ROWS_PER_CTA)

// x transposed to [i][16 tokens] as 4 float4 quads per i. 256 KB scratch.
__device__ float4 g_xT[IN_F * 4];

__global__ void transpose_x_kernel(const float* __restrict__ x) {
    int i = blockIdx.x * blockDim.x + threadIdx.x;
    float v[TOK];
#pragma unroll
    for (int t = 0; t < TOK; t++) v[t] = x[t * IN_F + i];
#pragma unroll
    for (int q = 0; q < 4; q++)
        g_xT[i * 4 + q] = make_float4(v[4*q], v[4*q+1], v[4*q+2], v[4*q+3]);
}

typedef unsigned long long u64;

__device__ __forceinline__ u64 pack2(float lo, float hi) {
    u64 r; asm("mov.b64 %0, {%1, %2};" : "=l"(r) : "f"(lo), "f"(hi)); return r;
}
__device__ __forceinline__ void unpack2(u64 v, float& lo, float& hi) {
    asm("mov.b64 {%0, %1}, %2;" : "=f"(lo), "=f"(hi) : "l"(v));
}
__device__ __forceinline__ void ffma2(u64& d, u64 a, u64 b) {
    asm("fma.rn.f32x2 %0, %1, %2, %0;" : "+l"(d) : "l"(a), "l"(b));
}
__device__ __forceinline__ u64 fadd2(u64 a, u64 b) {
    u64 r; asm("add.rn.f32x2 %0, %1, %2;" : "=l"(r) : "l"(a), "l"(b)); return r;
}

__global__ void __launch_bounds__(THREADS, 2) q4_gemm_kernel(
    const int*   __restrict__ wq,      // [OUT_F][IN_F] int32 nibbles 0..15
    const float* __restrict__ wscale,  // [OUT_F][IN_F/32]
    const float* __restrict__ bias,    // [OUT_F]
    float*       __restrict__ out)     // [TOK][OUT_F]
{
    // x tile: [quad][slot], XOR-swizzled slots -> conflict-free stride-4 LDS.128.
    __shared__ float4 xs[4][CHUNK];            // 32 KB
    __shared__ float  res[ROWS_PER_CTA][TOK + 1];

    const int tid  = threadIdx.x;
    const int warp = tid >> 5;
    const int lane = tid & 31;
    const int row0 = blockIdx.x * ROWS_PER_CTA + warp * RPW;

    u64 acc[RPW][8];
#pragma unroll
    for (int r = 0; r < RPW; r++)
#pragma unroll
        for (int k = 0; k < 8; k++) acc[r][k] = 0ull;

    // ---- depth-2 pipeline on weights: preload iteration 0 ----
    int4  qn[RPW]; float sn[RPW];
    {
        const int gi = lane * 4;
#pragma unroll
        for (int r = 0; r < RPW; r++) {
            qn[r] = __ldg((const int4*)(wq + (size_t)(row0 + r) * IN_F + gi));
            sn[r] = __ldg(wscale + (size_t)(row0 + r) * (IN_F / 32) + (gi >> 5));
        }
    }

    for (int c = 0; c < NCHUNK; c++) {
        const int cbase = c * CHUNK;

        // ---- stage x chunk (coalesced LDG.128, swizzled STS.128) ----
#pragma unroll
        for (int idx = tid; idx < CHUNK; idx += THREADS) {
            const float4* src = g_xT + (size_t)(cbase + idx) * 4;
            const int slot = idx ^ ((idx >> 3) & 7);
            float4 a0 = src[0], a1 = src[1], a2 = src[2], a3 = src[3];
            xs[0][slot] = a0; xs[1][slot] = a1; xs[2][slot] = a2; xs[3][slot] = a3;
        }
        __syncthreads();

#pragma unroll
        for (int it = 0; it < ITPC; it++) {
            const int itg = c * ITPC + it;

            // rotate pipeline: consume current, immediately issue next loads
            int4 qc[RPW]; float sc[RPW];
#pragma unroll
            for (int r = 0; r < RPW; r++) { qc[r] = qn[r]; sc[r] = sn[r]; }
            if (itg + 1 < NIT) {
                const int gi = (itg + 1) * 128 + lane * 4;
#pragma unroll
                for (int r = 0; r < RPW; r++) {
                    qn[r] = __ldg((const int4*)(wq + (size_t)(row0 + r) * IN_F + gi));
                    sn[r] = __ldg(wscale + (size_t)(row0 + r) * (IN_F / 32) + (gi >> 5));
                }
            }

            float m[RPW];
#pragma unroll
            for (int r = 0; r < RPW; r++) m[r] = sc[r] * -8.0f;

#pragma unroll
            for (int j = 0; j < 4; j++) {
                const int ii   = it * 128 + lane * 4 + j;
                const int slot = ii ^ ((ii >> 3) & 7);
                const float4 x0 = xs[0][slot];
                const float4 x1 = xs[1][slot];
                const float4 x2 = xs[2][slot];
                const float4 x3 = xs[3][slot];
                u64 xp[8];
                xp[0] = pack2(x0.x, x0.y); xp[1] = pack2(x0.z, x0.w);
                xp[2] = pack2(x1.x, x1.y); xp[3] = pack2(x1.z, x1.w);
                xp[4] = pack2(x2.x, x2.y); xp[5] = pack2(x2.z, x2.w);
                xp[6] = pack2(x3.x, x3.y); xp[7] = pack2(x3.z, x3.w);
#pragma unroll
                for (int r = 0; r < RPW; r++) {
                    const int q = (j == 0) ? qc[r].x : (j == 1) ? qc[r].y
                                : (j == 2) ? qc[r].z : qc[r].w;
                    // exact int->float without I2F: (2^23|q) - 2^23 == q
                    const float qf =
                        __uint_as_float(0x4B000000u | (unsigned)q) - 8388608.0f;
                    const float wf = fmaf(qf, sc[r], m[r]);   // RN((q-8)*s)
                    const u64 wp = pack2(wf, wf);
                    ffma2(acc[r][0], wp, xp[0]); ffma2(acc[r][1], wp, xp[1]);
                    ffma2(acc[r][2], wp, xp[2]); ffma2(acc[r][3], wp, xp[3]);
                    ffma2(acc[r][4], wp, xp[4]); ffma2(acc[r][5], wp, xp[5]);
                    ffma2(acc[r][6], wp, xp[6]); ffma2(acc[r][7], wp, xp[7]);
                }
            }
        }
        __syncthreads();
    }

    // ---- butterfly reduction (packed adds), stage to smem ----
#pragma unroll
    for (int r = 0; r < RPW; r++) {
#pragma unroll
        for (int k = 0; k < 8; k++) {
            u64 v = acc[r][k];
#pragma unroll
            for (int off = 16; off > 0; off >>= 1)
                v = fadd2(v, __shfl_xor_sync(0xffffffffu, v, off));
            if (lane == 0) {
                float lo, hi; unpack2(v, lo, hi);
                res[warp * RPW + r][2 * k]     = lo;
                res[warp * RPW + r][2 * k + 1] = hi;
            }
        }
    }
    __syncthreads();

    // ---- coalesced write-out with bias ----
    const int colbase = blockIdx.x * ROWS_PER_CTA;
#pragma unroll
    for (int idx = tid; idx < ROWS_PER_CTA * TOK; idx += THREADS) {
        const int t   = idx >> 5;       // token
        const int row = idx & 31;       // row within CTA
        out[(size_t)t * OUT_F + colbase + row] = res[row][t] + bias[colbase + row];
    }
}

extern "C" void kernel_launch(void* const* d_in, const int* in_sizes, int n_in,
                              void* d_out, int out_size) {
    const float* x      = (const float*)d_in[0];  // [16, 4096]
    const int*   wq     = (const int*)  d_in[1];  // [11008, 4096]
    const float* wscale = (const float*)d_in[2];  // [11008, 128]
    const float* bias   = (const float*)d_in[3];  // [11008]
    float* out = (float*)d_out;                   // [16, 11008]

    transpose_x_kernel<<<IN_F / 256, 256>>>(x);
    q4_gemm_kernel<<<NCTA, THREADS>>>(wq, wscale, bias, out);
}

// round 6
// speedup vs baseline: 1.4789x; 1.2679x over previous
#include <cuda_runtime.h>
#include <cuda_fp16.h>
#include <cstdint>

typedef unsigned int u32;

#define IN_F    4096
#define OUT_F   11008
#define TOK     16
#define THREADS 256
#define WARPS   8
#define KPER    (IN_F / WARPS)     // 512 k per warp
#define NCHUNK  (KPER / 16)        // 32 chunks of k=16
#define ROWS_PER_CTA 32
#define NCTA    (OUT_F / ROWS_PER_CTA)  // 344

// x split into fp16 hi/lo, packed as half2 k-pairs: [tok][IN_F/2]. 128 KB each.
__device__ u32 g_xh[TOK * (IN_F / 2)];
__device__ u32 g_xl[TOK * (IN_F / 2)];

__global__ void split_x_kernel(const float* __restrict__ x) {
    const int i = blockIdx.x * blockDim.x + threadIdx.x;   // pair index
    const float v0 = x[2 * i], v1 = x[2 * i + 1];
    const __half h0 = __float2half_rn(v0), h1 = __float2half_rn(v1);
    const __half2 hi = __halves2half2(h0, h1);             // .x = low bits
    const __half2 lo = __floats2half2_rn(v0 - __half2float(h0),
                                         v1 - __half2float(h1));
    g_xh[i] = *reinterpret_cast<const u32*>(&hi);
    g_xl[i] = *reinterpret_cast<const u32*>(&lo);
}

__device__ __forceinline__ float magicq(int q) {
    // exact int->float for q in [0,16): (2^23|q) - 2^23
    return __uint_as_float(0x4B000000u | (u32)q) - 8388608.0f;
}
__device__ __forceinline__ u32 h2u(__half2 h) { return *reinterpret_cast<u32*>(&h); }

__device__ __forceinline__ void mma16816(float* d, const u32* a, u32 b0, u32 b1) {
    asm volatile(
        "mma.sync.aligned.m16n8k16.row.col.f32.f16.f16.f32 "
        "{%0,%1,%2,%3}, {%4,%5,%6,%7}, {%8,%9}, {%0,%1,%2,%3};"
        : "+f"(d[0]), "+f"(d[1]), "+f"(d[2]), "+f"(d[3])
        : "r"(a[0]), "r"(a[1]), "r"(a[2]), "r"(a[3]), "r"(b0), "r"(b1));
}

__global__ void __launch_bounds__(THREADS, 2) q4_hmma_kernel(
    const int*   __restrict__ wq,      // [OUT_F][IN_F] int32 nibbles 0..15
    const float* __restrict__ wscale,  // [OUT_F][IN_F/32]
    const float* __restrict__ bias,    // [OUT_F]
    float*       __restrict__ out)     // [TOK][OUT_F]
{
    __shared__ float part[WARPS][TOK][ROWS_PER_CTA];   // 16 KB

    const int tid  = threadIdx.x;
    const int warp = tid >> 5;
    const int lane = tid & 31;
    const int g    = lane >> 2;        // group id 0..7
    const int tig  = lane & 3;         // thread-in-group
    const int rowbase = blockIdx.x * ROWS_PER_CTA;
    const int kbase   = warp * KPER;

    // bases (constant per-thread); tile/chunk offsets folded as immediates
    const int*   wbase = wq + (size_t)(rowbase + g) * IN_F + kbase + tig * 2;
    const float* sbase = wscale + (size_t)(rowbase + g) * (IN_F / 32) + (kbase >> 5);
    const u32*   xh    = g_xh + g * (IN_F / 2) + (kbase >> 1) + tig;
    const u32*   xl    = g_xl + g * (IN_F / 2) + (kbase >> 1) + tig;

    float acc[4][4];
#pragma unroll
    for (int t = 0; t < 4; t++)
#pragma unroll
        for (int i = 0; i < 4; i++) acc[t][i] = 0.0f;

    // ---- depth-2 register pipeline ----
    int2 qa0[4], qa1[4]; float sa[4];
    u32  Ah[4], Al[4];
#pragma unroll
    for (int t = 0; t < 4; t++) {
        qa0[t] = __ldg((const int2*)(wbase + (size_t)t * 8 * IN_F));
        qa1[t] = __ldg((const int2*)(wbase + (size_t)t * 8 * IN_F + 8));
        sa[t]  = __ldg(sbase + t * 8 * (IN_F / 32));
    }
    Ah[0] = __ldg(xh);            Ah[1] = __ldg(xh + 8 * (IN_F / 2));
    Ah[2] = __ldg(xh + 4);        Ah[3] = __ldg(xh + 8 * (IN_F / 2) + 4);
    Al[0] = __ldg(xl);            Al[1] = __ldg(xl + 8 * (IN_F / 2));
    Al[2] = __ldg(xl + 4);        Al[3] = __ldg(xl + 8 * (IN_F / 2) + 4);

    for (int c = 0; c < NCHUNK; c++) {
        int2 qb0[4], qb1[4]; float sb[4];
        u32  Bh[4], Bl[4];
        if (c + 1 < NCHUNK) {
            const int ko = (c + 1) * 16;
#pragma unroll
            for (int t = 0; t < 4; t++) {
                qb0[t] = __ldg((const int2*)(wbase + (size_t)t * 8 * IN_F + ko));
                qb1[t] = __ldg((const int2*)(wbase + (size_t)t * 8 * IN_F + ko + 8));
                sb[t]  = __ldg(sbase + t * 8 * (IN_F / 32) + ((c + 1) >> 1));
            }
            const int xo = (c + 1) * 8;
            Bh[0] = __ldg(xh + xo);     Bh[1] = __ldg(xh + 8 * (IN_F / 2) + xo);
            Bh[2] = __ldg(xh + xo + 4); Bh[3] = __ldg(xh + 8 * (IN_F / 2) + xo + 4);
            Bl[0] = __ldg(xl + xo);     Bl[1] = __ldg(xl + 8 * (IN_F / 2) + xo);
            Bl[2] = __ldg(xl + xo + 4); Bl[3] = __ldg(xl + 8 * (IN_F / 2) + xo + 4);
        }

#pragma unroll
        for (int t = 0; t < 4; t++) {
            const float s = sa[t];
            const float m = s * -8.0f;
            const float w0 = fmaf(magicq(qa0[t].x), s, m);   // k+0
            const float w1 = fmaf(magicq(qa0[t].y), s, m);   // k+1
            const float w2 = fmaf(magicq(qa1[t].x), s, m);   // k+8
            const float w3 = fmaf(magicq(qa1[t].y), s, m);   // k+9
            const __half2 bh0 = __floats2half2_rn(w0, w1);
            const __half2 bh1 = __floats2half2_rn(w2, w3);
            const float2 f0 = __half22float2(bh0);
            const float2 f1 = __half22float2(bh1);
            const __half2 bl0 = __floats2half2_rn(w0 - f0.x, w1 - f0.y);
            const __half2 bl1 = __floats2half2_rn(w2 - f1.x, w3 - f1.y);
            mma16816(acc[t], Ah, h2u(bh0), h2u(bh1));   // wh * xh
            mma16816(acc[t], Al, h2u(bh0), h2u(bh1));   // wh * xl
            mma16816(acc[t], Ah, h2u(bl0), h2u(bl1));   // wl * xh
        }
#pragma unroll
        for (int t = 0; t < 4; t++) { qa0[t] = qb0[t]; qa1[t] = qb1[t]; sa[t] = sb[t]; }
#pragma unroll
        for (int i = 0; i < 4; i++) { Ah[i] = Bh[i]; Al[i] = Bl[i]; }
    }

    // ---- stage partials: D[m=tok, n=row] fragments -> smem ----
#pragma unroll
    for (int t = 0; t < 4; t++) {
        const int col = t * 8 + tig * 2;
        *(float2*)&part[warp][g][col]     = make_float2(acc[t][0], acc[t][1]);
        *(float2*)&part[warp][g + 8][col] = make_float2(acc[t][2], acc[t][3]);
    }
    __syncthreads();

    // ---- 8-way k-reduction + bias, coalesced store ----
#pragma unroll
    for (int idx = tid; idx < TOK * ROWS_PER_CTA; idx += THREADS) {
        const int row = idx & 31;
        const int t   = idx >> 5;
        float v = bias[rowbase + row];
#pragma unroll
        for (int w = 0; w < WARPS; w++) v += part[w][t][row];
        out[(size_t)t * OUT_F + rowbase + row] = v;
    }
}

extern "C" void kernel_launch(void* const* d_in, const int* in_sizes, int n_in,
                              void* d_out, int out_size) {
    const float* x      = (const float*)d_in[0];  // [16, 4096]
    const int*   wq     = (const int*)  d_in[1];  // [11008, 4096]
    const float* wscale = (const float*)d_in[2];  // [11008, 128]
    const float* bias   = (const float*)d_in[3];  // [11008]
    float* out = (float*)d_out;                   // [16, 11008]

    split_x_kernel<<<(TOK * IN_F / 2) / 256, 256>>>(x);
    q4_hmma_kernel<<<NCTA, THREADS>>>(wq, wscale, bias, out);
}

// round 7
// speedup vs baseline: 1.5966x; 1.0796x over previous
#include <cuda_runtime.h>
#include <cuda_fp16.h>
#include <cstdint>

typedef unsigned int u32;

#define IN_F    4096
#define OUT_F   11008
#define TOK     16
#define THREADS 256
#define NTILE   64                    // output rows per CTA
#define NCTA_N  (OUT_F / NTILE)       // 172
#define KSPLIT  4
#define KPER    (IN_F / KSPLIT)       // 1024
#define KCHUNK  32
#define NCHUNK  (KPER / KCHUNK)       // 32

// x split to fp16 hi/lo, [tok][IN_F/2] u32 half2 k-pairs (128 KB each, L2-resident)
__device__ u32 g_xh[TOK * (IN_F / 2)];
__device__ u32 g_xl[TOK * (IN_F / 2)];
// w_scale transposed: [block][row]
__device__ float g_wsT[(IN_F / 32) * OUT_F];
// k-split partials
__device__ float g_part[KSPLIT][TOK][OUT_F];

__global__ void split_x_kernel(const float* __restrict__ x) {
    const int i = blockIdx.x * blockDim.x + threadIdx.x;
    const float v0 = x[2 * i], v1 = x[2 * i + 1];
    const __half h0 = __float2half_rn(v0), h1 = __float2half_rn(v1);
    const __half2 hi = __halves2half2(h0, h1);
    const __half2 lo = __floats2half2_rn(v0 - __half2float(h0),
                                         v1 - __half2float(h1));
    g_xh[i] = *reinterpret_cast<const u32*>(&hi);
    g_xl[i] = *reinterpret_cast<const u32*>(&lo);
}

__global__ void transpose_ws_kernel(const float* __restrict__ ws) {
    __shared__ float tile[32][33];
    const int r = blockIdx.x * 32 + threadIdx.y;   // row
    const int b = blockIdx.y * 32 + threadIdx.x;   // block
    tile[threadIdx.y][threadIdx.x] = ws[(size_t)r * (IN_F / 32) + b];
    __syncthreads();
    const int ob = blockIdx.y * 32 + threadIdx.y;
    const int orr = blockIdx.x * 32 + threadIdx.x;
    g_wsT[(size_t)ob * OUT_F + orr] = tile[threadIdx.x][threadIdx.y];
}

__device__ __forceinline__ float magicq(int q) {
    return __uint_as_float(0x4B000000u | (u32)q) - 8388608.0f;  // exact for 0..15
}
__device__ __forceinline__ u32 h2u(__half2 h) { return *reinterpret_cast<u32*>(&h); }

__device__ __forceinline__ void mma16816(float* d, const u32* a, u32 b0, u32 b1) {
    asm volatile(
        "mma.sync.aligned.m16n8k16.row.col.f32.f16.f16.f32 "
        "{%0,%1,%2,%3}, {%4,%5,%6,%7}, {%8,%9}, {%0,%1,%2,%3};"
        : "+f"(d[0]), "+f"(d[1]), "+f"(d[2]), "+f"(d[3])
        : "r"(a[0]), "r"(a[1]), "r"(a[2]), "r"(a[3]), "r"(b0), "r"(b1));
}
__device__ __forceinline__ void ldsm4(u32* r, u32 a) {
    asm volatile("ldmatrix.sync.aligned.m8n8.x4.shared.b16 {%0,%1,%2,%3}, [%4];"
                 : "=r"(r[0]), "=r"(r[1]), "=r"(r[2]), "=r"(r[3]) : "r"(a));
}
__device__ __forceinline__ void ldsm2(u32* r, u32 a) {
    asm volatile("ldmatrix.sync.aligned.m8n8.x2.shared.b16 {%0,%1}, [%2];"
                 : "=r"(r[0]), "=r"(r[1]) : "r"(a));
}

// smem: wt[buf][plane][n=64][32 halves] (swizzled units), xt[buf][plane][m=16][32]
struct __align__(128) Smem {
    __half wt[2][2][NTILE][32];   // 16 KB
    __half xt[2][2][TOK][32];     //  4 KB
};

__device__ __forceinline__ void dq_store(char* hbase, char* lbase, int off,
                                         int4 q, float s) {
    const float m  = s * -8.0f;
    const float w0 = fmaf(magicq(q.x), s, m);
    const float w1 = fmaf(magicq(q.y), s, m);
    const float w2 = fmaf(magicq(q.z), s, m);
    const float w3 = fmaf(magicq(q.w), s, m);
    const __half2 h01 = __floats2half2_rn(w0, w1);
    const __half2 h23 = __floats2half2_rn(w2, w3);
    const float2 f01 = __half22float2(h01);
    const float2 f23 = __half22float2(h23);
    const __half2 l01 = __floats2half2_rn(w0 - f01.x, w1 - f01.y);
    const __half2 l23 = __floats2half2_rn(w2 - f23.x, w3 - f23.y);
    *(uint2*)(hbase + off) = make_uint2(h2u(h01), h2u(h23));
    *(uint2*)(lbase + off) = make_uint2(h2u(l01), h2u(l23));
}

__global__ void __launch_bounds__(THREADS, 3) q4_hmma2_kernel(
    const int* __restrict__ wq)      // [OUT_F][IN_F] int32 nibbles 0..15
{
    __shared__ Smem sm;

    const int tid  = threadIdx.x;
    const int warp = tid >> 5;
    const int lane = tid & 31;
    const int growbase = blockIdx.x * NTILE;
    const int ks    = blockIdx.y;
    const int kbase = ks * KPER;

    // ---- W load mapping: 8 lanes per row, each LDG.128 = 4 rows x 1 line ----
    const int wr  = tid >> 3;                      // 0..31 (and +32)
    const int wqd = tid & 7;                       // k-quad within chunk
    const int* wptr = wq + (size_t)(growbase + wr) * IN_F + kbase + 4 * wqd;
    const float* sptr = g_wsT + (size_t)(ks * (KPER / 32)) * OUT_F + growbase + wr;

    // ---- x load mapping (threads < 128): plane, token, unit ----
    const int xp = tid >> 6;                       // 0 hi, 1 lo
    const int xm = (tid >> 2) & 15;
    const int xu = tid & 3;
    const u32* xsrc = (xp ? g_xl : g_xh) + xm * (IN_F / 2) + ks * (KPER / 2) + xu * 4;

    const u32 wt_base = (u32)__cvta_generic_to_shared(&sm.wt[0][0][0][0]);
    const u32 xt_base = (u32)__cvta_generic_to_shared(&sm.xt[0][0][0][0]);

    float acc[4] = {0.f, 0.f, 0.f, 0.f};

    // ---- prologue: chunk 0 ----
    int4 qa0 = __ldg((const int4*)wptr);
    int4 qa1 = __ldg((const int4*)(wptr + 32 * IN_F));
    float sa0 = __ldg(sptr), sa1 = __ldg(sptr + 32);
    int4 xa = make_int4(0, 0, 0, 0);
    if (tid < 128) xa = __ldg((const int4*)xsrc);

    for (int c = 0; c < NCHUNK; c++) {
        const int buf = c & 1;

        // ---- dequant + STS into tiles[buf] ----
        {
            const int u = wqd >> 1, h = wqd & 1;
            char* base = (char*)&sm.wt[buf][0][0][0];
            const int off0 = wr * 64 + ((u ^ ((wr >> 1) & 3)) << 4) + (h << 3);
            dq_store(base + off0, base + 4096 + off0, 0, qa0, sa0);
            const int r1 = wr + 32;
            const int off1 = r1 * 64 + ((u ^ ((r1 >> 1) & 3)) << 4) + (h << 3);
            dq_store(base + off1, base + 4096 + off1, 0, qa1, sa1);
        }
        if (tid < 128) {
            char* xb = (char*)&sm.xt[buf][xp][xm][0];
            *(int4*)(xb + ((xu ^ ((xm >> 1) & 3)) << 4)) = xa;
        }

        // ---- prefetch chunk c+1 (issued before the barrier) ----
        if (c + 1 < NCHUNK) {
            qa0 = __ldg((const int4*)(wptr + (c + 1) * KCHUNK));
            qa1 = __ldg((const int4*)(wptr + 32 * IN_F + (c + 1) * KCHUNK));
            sa0 = __ldg(sptr + (size_t)(c + 1) * OUT_F);
            sa1 = __ldg(sptr + (size_t)(c + 1) * OUT_F + 32);
            if (tid < 128) xa = __ldg((const int4*)(xsrc + (c + 1) * (KCHUNK / 2)));
        }
        __syncthreads();

        // ---- fragments + MMAs for chunk c ----
        const u32 wtb = wt_base + buf * 8192;
        const u32 xtb = xt_base + buf * 2048;
        const int i = lane & 7;
#pragma unroll
        for (int s = 0; s < 2; s++) {
            // A fragments (x): x4, matrices {m0-7,k0-7},{m8-15,k0-7},{m0-7,k8-15},{m8-15,k8-15}
            const int jj = lane >> 3;
            const int am = i + ((jj & 1) << 3);
            const int au = 2 * s + (jj >> 1);
            const u32 aoff = am * 64 + ((au ^ ((am >> 1) & 3)) << 4);
            u32 ah[4], al[4];
            ldsm4(ah, xtb + aoff);
            ldsm4(al, xtb + 1024 + aoff);
            // B fragments (w): x2, rows = warp's n8
            const int bj = (lane >> 3) & 1;
            const int bn = (warp << 3) + i;
            const int bu = 2 * s + bj;
            const u32 boff = bn * 64 + ((bu ^ ((bn >> 1) & 3)) << 4);
            u32 bh[2], bl[2];
            ldsm2(bh, wtb + boff);
            ldsm2(bl, wtb + 4096 + boff);

            mma16816(acc, ah, bh[0], bh[1]);   // wh * xh
            mma16816(acc, al, bh[0], bh[1]);   // wh * xl
            mma16816(acc, ah, bl[0], bl[1]);   // wl * xh
        }
    }

    // ---- epilogue: write partials ----
    const int m    = lane >> 2;
    const int grow = growbase + (warp << 3) + ((lane & 3) << 1);
    *(float2*)&g_part[ks][m][grow]     = make_float2(acc[0], acc[1]);
    *(float2*)&g_part[ks][m + 8][grow] = make_float2(acc[2], acc[3]);
}

__global__ void reduce_kernel(const float* __restrict__ bias, float* __restrict__ out) {
    const int r = blockIdx.x * 256 + threadIdx.x;   // 43*256 = 11008 exact
    const int t = blockIdx.y;
    float v = bias[r];
#pragma unroll
    for (int ks = 0; ks < KSPLIT; ks++) v += g_part[ks][t][r];
    out[(size_t)t * OUT_F + r] = v;
}

extern "C" void kernel_launch(void* const* d_in, const int* in_sizes, int n_in,
                              void* d_out, int out_size) {
    const float* x      = (const float*)d_in[0];  // [16, 4096]
    const int*   wq     = (const int*)  d_in[1];  // [11008, 4096]
    const float* wscale = (const float*)d_in[2];  // [11008, 128]
    const float* bias   = (const float*)d_in[3];  // [11008]
    float* out = (float*)d_out;                   // [16, 11008]

    split_x_kernel<<<(TOK * IN_F / 2) / 256, 256>>>(x);
    transpose_ws_kernel<<<dim3(OUT_F / 32, (IN_F / 32) / 32), dim3(32, 32)>>>(wscale);
    q4_hmma2_kernel<<<dim3(NCTA_N, KSPLIT), THREADS>>>(wq);
    reduce_kernel<<<dim3(OUT_F / 256, TOK), 256>>>(bias, out);
}

// round 8
// speedup vs baseline: 1.7670x; 1.1067x over previous
#include <cuda_runtime.h>
#include <cuda_fp16.h>
#include <cstdint>

typedef unsigned int u32;

#define IN_F    4096
#define OUT_F   11008
#define TOK     16
#define THREADS 256
#define NTILE   64                    // output rows per CTA
#define NCTA_N  (OUT_F / NTILE)       // 172
#define KSPLIT  4
#define KPER    (IN_F / KSPLIT)       // 1024
#define KCHUNK  32
#define NCHUNK  (KPER / KCHUNK)       // 32

// x split to fp16 hi/lo, [tok][IN_F/2] u32 half2 k-pairs (L2-resident)
__device__ u32 g_xh[TOK * (IN_F / 2)];
__device__ u32 g_xl[TOK * (IN_F / 2)];
// w_scale transposed: [block][row]
__device__ float g_wsT[(IN_F / 32) * OUT_F];
// k-split partials
__device__ float g_part[KSPLIT][TOK][OUT_F];

__global__ void split_x_kernel(const float* __restrict__ x) {
    const int i = blockIdx.x * blockDim.x + threadIdx.x;
    const float v0 = x[2 * i], v1 = x[2 * i + 1];
    const __half h0 = __float2half_rn(v0), h1 = __float2half_rn(v1);
    const __half2 hi = __halves2half2(h0, h1);
    const __half2 lo = __floats2half2_rn(v0 - __half2float(h0),
                                         v1 - __half2float(h1));
    g_xh[i] = *reinterpret_cast<const u32*>(&hi);
    g_xl[i] = *reinterpret_cast<const u32*>(&lo);
}

__global__ void transpose_ws_kernel(const float* __restrict__ ws) {
    __shared__ float tile[32][33];
    const int r = blockIdx.x * 32 + threadIdx.y;   // row
    const int b = blockIdx.y * 32 + threadIdx.x;   // block
    tile[threadIdx.y][threadIdx.x] = ws[(size_t)r * (IN_F / 32) + b];
    __syncthreads();
    const int ob  = blockIdx.y * 32 + threadIdx.y;
    const int orr = blockIdx.x * 32 + threadIdx.x;
    g_wsT[(size_t)ob * OUT_F + orr] = tile[threadIdx.x][threadIdx.y];
}

__device__ __forceinline__ u32 h2u(__half2 h) { return *reinterpret_cast<u32*>(&h); }
__device__ __forceinline__ __half2 u2h(u32 v) { return *reinterpret_cast<__half2*>(&v); }

__device__ __forceinline__ void mma16816(float* d, const u32* a, u32 b0, u32 b1) {
    asm volatile(
        "mma.sync.aligned.m16n8k16.row.col.f32.f16.f16.f32 "
        "{%0,%1,%2,%3}, {%4,%5,%6,%7}, {%8,%9}, {%0,%1,%2,%3};"
        : "+f"(d[0]), "+f"(d[1]), "+f"(d[2]), "+f"(d[3])
        : "r"(a[0]), "r"(a[1]), "r"(a[2]), "r"(a[3]), "r"(b0), "r"(b1));
}
__device__ __forceinline__ void mma16816_z(float* d, const u32* a, u32 b0, u32 b1) {
    asm volatile(
        "mma.sync.aligned.m16n8k16.row.col.f32.f16.f16.f32 "
        "{%0,%1,%2,%3}, {%4,%5,%6,%7}, {%8,%9}, {%10,%10,%10,%10};"
        : "=f"(d[0]), "=f"(d[1]), "=f"(d[2]), "=f"(d[3])
        : "r"(a[0]), "r"(a[1]), "r"(a[2]), "r"(a[3]), "r"(b0), "r"(b1), "f"(0.0f));
}
__device__ __forceinline__ void ldsm4(u32* r, u32 a) {
    asm volatile("ldmatrix.sync.aligned.m8n8.x4.shared.b16 {%0,%1,%2,%3}, [%4];"
                 : "=r"(r[0]), "=r"(r[1]), "=r"(r[2]), "=r"(r[3]) : "r"(a));
}
__device__ __forceinline__ void ldsm2(u32* r, u32 a) {
    asm volatile("ldmatrix.sync.aligned.m8n8.x2.shared.b16 {%0,%1}, [%2];"
                 : "=r"(r[0]), "=r"(r[1]) : "r"(a));
}

// smem: wt[buf][n=64][32 halves] int-valued fp16; xt[buf][plane][m=16][32]; scales
struct __align__(128) Smem {
    __half wt[2][NTILE][32];      //  8 KB
    __half xt[2][2][TOK][32];     //  4 KB
    float  sc[NCHUNK][NTILE];     //  8 KB
};

// nibble-pair -> fp16 integers (q-8), exact: (0x6400|q) is 1024+q; minus 1032
__device__ __forceinline__ void dq_sts(char* base, int off, int4 q) {
    const __half2 k1032 = u2h(0x64086408u);
    const u32 t0 = ((u32)q.x | ((u32)q.y << 16)) | 0x64006400u;
    const u32 t1 = ((u32)q.z | ((u32)q.w << 16)) | 0x64006400u;
    const __half2 h0 = __hsub2(u2h(t0), k1032);
    const __half2 h1 = __hsub2(u2h(t1), k1032);
    *(uint2*)(base + off) = make_uint2(h2u(h0), h2u(h1));
}

__global__ void __launch_bounds__(THREADS, 4) q4_hmma3_kernel(
    const int* __restrict__ wq)      // [OUT_F][IN_F] int32 nibbles 0..15
{
    __shared__ Smem sm;

    const int tid  = threadIdx.x;
    const int warp = tid >> 5;
    const int lane = tid & 31;
    const int growbase = blockIdx.x * NTILE;
    const int ks    = blockIdx.y;
    const int kbase = ks * KPER;

    // W mapping: 8 lanes per row (int4 each), LDG covers full 128B lines
    const int wr  = tid >> 3;                      // 0..31 (and +32)
    const int wqd = tid & 7;                       // k-quad within chunk
    const int* wptr = wq + (size_t)(growbase + wr) * IN_F + kbase + 4 * wqd;

    // x mapping (threads < 128): plane, token, unit
    const int xp = tid >> 6;
    const int xm = (tid >> 2) & 15;
    const int xu = tid & 3;
    const u32* xsrc = (xp ? g_xl : g_xh) + xm * (IN_F / 2) + ks * (KPER / 2) + xu * 4;

    // stage scale tile once: [chunk][row], coalesced
    for (int idx = tid; idx < NCHUNK * NTILE; idx += THREADS) {
        const int cc = idx >> 6, rr = idx & 63;
        sm.sc[cc][rr] = __ldg(g_wsT + (size_t)(ks * NCHUNK + cc) * OUT_F + growbase + rr);
    }

    const u32 wt_base = (u32)__cvta_generic_to_shared(&sm.wt[0][0][0]);
    const u32 xt_base = (u32)__cvta_generic_to_shared(&sm.xt[0][0][0][0]);

    float acc[4] = {0.f, 0.f, 0.f, 0.f};

    // ---- prologue: lookahead-2 ----
    int4 qA[2][2]; int4 xA[2];
#pragma unroll
    for (int p = 0; p < 2; p++) {
        qA[p][0] = __ldg((const int4*)(wptr + p * KCHUNK));
        qA[p][1] = __ldg((const int4*)(wptr + 32 * IN_F + p * KCHUNK));
        if (tid < 128) xA[p] = __ldg((const int4*)(xsrc + p * (KCHUNK / 2)));
    }
    __syncthreads();   // scale tile ready (also covers before first use)

    const int n0 = (warp << 3) + ((lane & 3) << 1);   // this thread's n pair

    for (int c = 0; c < NCHUNK; c++) {
        const int slot = c & 1;

        // ---- convert + STS chunk c ----
        {
            const int u = wqd >> 1, h = wqd & 1;
            char* base = (char*)&sm.wt[slot][0][0];
            const int off0 = wr * 64 + ((u ^ ((wr >> 1) & 3)) << 4) + (h << 3);
            dq_sts(base, off0, qA[slot][0]);
            const int r1 = wr + 32;
            const int off1 = r1 * 64 + ((u ^ ((r1 >> 1) & 3)) << 4) + (h << 3);
            dq_sts(base, off1, qA[slot][1]);
        }
        if (tid < 128) {
            char* xb = (char*)&sm.xt[slot][xp][xm][0];
            *(int4*)(xb + ((xu ^ ((xm >> 1) & 3)) << 4)) = xA[slot];
        }

        // ---- prefetch chunk c+2 into freed slot ----
        if (c + 2 < NCHUNK) {
            qA[slot][0] = __ldg((const int4*)(wptr + (c + 2) * KCHUNK));
            qA[slot][1] = __ldg((const int4*)(wptr + 32 * IN_F + (c + 2) * KCHUNK));
            if (tid < 128) xA[slot] = __ldg((const int4*)(xsrc + (c + 2) * (KCHUNK / 2)));
        }
        __syncthreads();

        // ---- fragments + 4 MMAs (integer weights, exact) ----
        const u32 wtb = wt_base + slot * 4096;
        const u32 xtb = xt_base + slot * 2048;
        const int i  = lane & 7;
        const int jj = lane >> 3;
        float pd[4];
#pragma unroll
        for (int s = 0; s < 2; s++) {
            const int am = i + ((jj & 1) << 3);
            const int au = 2 * s + (jj >> 1);
            const u32 aoff = am * 64 + ((au ^ ((am >> 1) & 3)) << 4);
            u32 ah[4], al[4];
            ldsm4(ah, xtb + aoff);
            ldsm4(al, xtb + 1024 + aoff);
            const int bj = jj & 1;
            const int bn = (warp << 3) + i;
            const int bu = 2 * s + bj;
            const u32 boff = bn * 64 + ((bu ^ ((bn >> 1) & 3)) << 4);
            u32 b[2];
            ldsm2(b, wtb + boff);
            if (s == 0) mma16816_z(pd, ah, b[0], b[1]);
            else        mma16816  (pd, ah, b[0], b[1]);
            mma16816(pd, al, b[0], b[1]);
        }
        // ---- per-chunk scale (one scale per 32-k block per row) ----
        const float2 sv = *(const float2*)&sm.sc[c][n0];
        acc[0] = fmaf(pd[0], sv.x, acc[0]);
        acc[1] = fmaf(pd[1], sv.y, acc[1]);
        acc[2] = fmaf(pd[2], sv.x, acc[2]);
        acc[3] = fmaf(pd[3], sv.y, acc[3]);
    }

    // ---- epilogue: write partials ----
    const int m    = lane >> 2;
    const int grow = growbase + n0;
    *(float2*)&g_part[ks][m][grow]     = make_float2(acc[0], acc[1]);
    *(float2*)&g_part[ks][m + 8][grow] = make_float2(acc[2], acc[3]);
}

__global__ void reduce_kernel(const float* __restrict__ bias, float* __restrict__ out) {
    const int r = blockIdx.x * 256 + threadIdx.x;   // 43*256 = 11008 exact
    const int t = blockIdx.y;
    float v = bias[r];
#pragma unroll
    for (int ks = 0; ks < KSPLIT; ks++) v += g_part[ks][t][r];
    out[(size_t)t * OUT_F + r] = v;
}

extern "C" void kernel_launch(void* const* d_in, const int* in_sizes, int n_in,
                              void* d_out, int out_size) {
    const float* x      = (const float*)d_in[0];  // [16, 4096]
    const int*   wq     = (const int*)  d_in[1];  // [11008, 4096]
    const float* wscale = (const float*)d_in[2];  // [11008, 128]
    const float* bias   = (const float*)d_in[3];  // [11008]
    float* out = (float*)d_out;                   // [16, 11008]

    split_x_kernel<<<(TOK * IN_F / 2) / 256, 256>>>(x);
    transpose_ws_kernel<<<dim3(OUT_F / 32, (IN_F / 32) / 32), dim3(32, 32)>>>(wscale);
    q4_hmma3_kernel<<<dim3(NCTA_N, KSPLIT), THREADS>>>(wq);
    reduce_kernel<<<dim3(OUT_F / 256, TOK), 256>>>(bias, out);
}

// round 9
// speedup vs baseline: 2.0307x; 1.1492x over previous
#include <cuda_runtime.h>
#include <cuda_fp16.h>
#include <cstdint>

typedef unsigned int u32;

#define IN_F    4096
#define OUT_F   11008
#define TOK     16
#define THREADS 256
#define NTILE   64                    // output rows per CTA
#define NCTA_N  (OUT_F / NTILE)       // 172
#define KSPLIT  16
#define KPER    (IN_F / KSPLIT)       // 256
#define KCHUNK  32
#define NCHUNK  (KPER / KCHUNK)       // 8

// x split to fp16 hi/lo, [tok][IN_F/2] u32 half2 k-pairs (L2-resident)
__device__ u32 g_xh[TOK * (IN_F / 2)];
__device__ u32 g_xl[TOK * (IN_F / 2)];
// k-split partials (11.3 MB)
__device__ float g_part[KSPLIT][TOK][OUT_F];

__global__ void split_x_kernel(const float* __restrict__ x) {
    const int i = blockIdx.x * blockDim.x + threadIdx.x;
    const float v0 = x[2 * i], v1 = x[2 * i + 1];
    const __half h0 = __float2half_rn(v0), h1 = __float2half_rn(v1);
    const __half2 hi = __halves2half2(h0, h1);
    const __half2 lo = __floats2half2_rn(v0 - __half2float(h0),
                                         v1 - __half2float(h1));
    g_xh[i] = *reinterpret_cast<const u32*>(&hi);
    g_xl[i] = *reinterpret_cast<const u32*>(&lo);
}

__device__ __forceinline__ u32 h2u(__half2 h) { return *reinterpret_cast<u32*>(&h); }
__device__ __forceinline__ __half2 u2h(u32 v) { return *reinterpret_cast<__half2*>(&v); }

__device__ __forceinline__ void mma16816(float* d, const u32* a, u32 b0, u32 b1) {
    asm volatile(
        "mma.sync.aligned.m16n8k16.row.col.f32.f16.f16.f32 "
        "{%0,%1,%2,%3}, {%4,%5,%6,%7}, {%8,%9}, {%0,%1,%2,%3};"
        : "+f"(d[0]), "+f"(d[1]), "+f"(d[2]), "+f"(d[3])
        : "r"(a[0]), "r"(a[1]), "r"(a[2]), "r"(a[3]), "r"(b0), "r"(b1));
}
__device__ __forceinline__ void mma16816_z(float* d, const u32* a, u32 b0, u32 b1) {
    asm volatile(
        "mma.sync.aligned.m16n8k16.row.col.f32.f16.f16.f32 "
        "{%0,%1,%2,%3}, {%4,%5,%6,%7}, {%8,%9}, {%10,%10,%10,%10};"
        : "=f"(d[0]), "=f"(d[1]), "=f"(d[2]), "=f"(d[3])
        : "r"(a[0]), "r"(a[1]), "r"(a[2]), "r"(a[3]), "r"(b0), "r"(b1), "f"(0.0f));
}
__device__ __forceinline__ void ldsm4(u32* r, u32 a) {
    asm volatile("ldmatrix.sync.aligned.m8n8.x4.shared.b16 {%0,%1,%2,%3}, [%4];"
                 : "=r"(r[0]), "=r"(r[1]), "=r"(r[2]), "=r"(r[3]) : "r"(a));
}
__device__ __forceinline__ void ldsm2(u32* r, u32 a) {
    asm volatile("ldmatrix.sync.aligned.m8n8.x2.shared.b16 {%0,%1}, [%2];"
                 : "=r"(r[0]), "=r"(r[1]) : "r"(a));
}

// smem: wt[buf][n=64][32 halves] int-valued fp16; xt[buf][plane][m=16][32]; scales
struct __align__(128) Smem {
    __half wt[2][NTILE][32];        //  8 KB
    __half xt[2][2][TOK][32];       //  4 KB
    float  sc[NCHUNK][NTILE];       //  2 KB  [k-block][row]
};

// nibble-pair -> fp16 integers (q-8), exact: (0x6400|q) is 1024+q; minus 1032
__device__ __forceinline__ void dq_sts(char* base, int off, int4 q) {
    const __half2 k1032 = u2h(0x64086408u);
    const u32 t0 = ((u32)q.x | ((u32)q.y << 16)) | 0x64006400u;
    const u32 t1 = ((u32)q.z | ((u32)q.w << 16)) | 0x64006400u;
    const __half2 h0 = __hsub2(u2h(t0), k1032);
    const __half2 h1 = __hsub2(u2h(t1), k1032);
    *(uint2*)(base + off) = make_uint2(h2u(h0), h2u(h1));
}

__global__ void __launch_bounds__(THREADS, 4) q4_hmma4_kernel(
    const int*   __restrict__ wq,        // [OUT_F][IN_F] int32 nibbles 0..15
    const float* __restrict__ wscale)    // [OUT_F][IN_F/32]
{
    __shared__ Smem sm;

    const int tid  = threadIdx.x;
    const int warp = tid >> 5;
    const int lane = tid & 31;
    const int growbase = blockIdx.x * NTILE;
    const int ks    = blockIdx.y;
    const int kbase = ks * KPER;

    // W mapping: 8 lanes per row (int4 each); warp-instr covers 4 full 128B lines
    const int wr  = tid >> 3;                      // 0..31 (and +32)
    const int wqd = tid & 7;                       // k-quad within chunk
    const int* wptr = wq + (size_t)(growbase + wr) * IN_F + kbase + 4 * wqd;

    // x mapping (threads < 128): plane, token, unit
    const int xp = tid >> 6;
    const int xm = (tid >> 2) & 15;
    const int xu = tid & 3;
    const u32* xsrc = (xp ? g_xl : g_xh) + xm * (IN_F / 2) + ks * (KPER / 2) + xu * 4;

    // stage scales straight from original layout: [row][block] -> sc[block][row]
    // (r-major read keeps 4 lines / warp-instr; smem transpose is 2 instrs)
    for (int idx = tid; idx < NTILE * NCHUNK; idx += THREADS) {   // 2 iters
        const int r = idx >> 3, b = idx & 7;
        sm.sc[b][r] = __ldg(wscale + (size_t)(growbase + r) * (IN_F / 32) + ks * NCHUNK + b);
    }

    const u32 wt_base = (u32)__cvta_generic_to_shared(&sm.wt[0][0][0]);
    const u32 xt_base = (u32)__cvta_generic_to_shared(&sm.xt[0][0][0][0]);

    float acc[4] = {0.f, 0.f, 0.f, 0.f};

    // ---- prologue: lookahead-2 ----
    int4 qA[2][2]; int4 xA[2];
#pragma unroll
    for (int p = 0; p < 2; p++) {
        qA[p][0] = __ldg((const int4*)(wptr + p * KCHUNK));
        qA[p][1] = __ldg((const int4*)(wptr + 32 * IN_F + p * KCHUNK));
        if (tid < 128) xA[p] = __ldg((const int4*)(xsrc + p * (KCHUNK / 2)));
    }
    __syncthreads();   // scale tile ready

    const int n0 = (warp << 3) + ((lane & 3) << 1);   // this thread's n pair

#pragma unroll
    for (int c = 0; c < NCHUNK; c++) {
        const int slot = c & 1;

        // ---- convert + STS chunk c ----
        {
            const int u = wqd >> 1, h = wqd & 1;
            char* base = (char*)&sm.wt[slot][0][0];
            const int off0 = wr * 64 + ((u ^ ((wr >> 1) & 3)) << 4) + (h << 3);
            dq_sts(base, off0, qA[slot][0]);
            const int r1 = wr + 32;
            const int off1 = r1 * 64 + ((u ^ ((r1 >> 1) & 3)) << 4) + (h << 3);
            dq_sts(base, off1, qA[slot][1]);
        }
        if (tid < 128) {
            char* xb = (char*)&sm.xt[slot][xp][xm][0];
            *(int4*)(xb + ((xu ^ ((xm >> 1) & 3)) << 4)) = xA[slot];
        }

        // ---- prefetch chunk c+2 into freed slot ----
        if (c + 2 < NCHUNK) {
            qA[slot][0] = __ldg((const int4*)(wptr + (c + 2) * KCHUNK));
            qA[slot][1] = __ldg((const int4*)(wptr + 32 * IN_F + (c + 2) * KCHUNK));
            if (tid < 128) xA[slot] = __ldg((const int4*)(xsrc + (c + 2) * (KCHUNK / 2)));
        }
        __syncthreads();

        // ---- fragments + 4 MMAs (integer weights, exact) ----
        const u32 wtb = wt_base + slot * 4096;
        const u32 xtb = xt_base + slot * 2048;
        const int i  = lane & 7;
        const int jj = lane >> 3;
        float pd[4];
#pragma unroll
        for (int s = 0; s < 2; s++) {
            const int am = i + ((jj & 1) << 3);
            const int au = 2 * s + (jj >> 1);
            const u32 aoff = am * 64 + ((au ^ ((am >> 1) & 3)) << 4);
            u32 ah[4], al[4];
            ldsm4(ah, xtb + aoff);
            ldsm4(al, xtb + 1024 + aoff);
            const int bj = jj & 1;
            const int bn = (warp << 3) + i;
            const int bu = 2 * s + bj;
            const u32 boff = bn * 64 + ((bu ^ ((bn >> 1) & 3)) << 4);
            u32 b[2];
            ldsm2(b, wtb + boff);
            if (s == 0) mma16816_z(pd, ah, b[0], b[1]);
            else        mma16816  (pd, ah, b[0], b[1]);
            mma16816(pd, al, b[0], b[1]);
        }
        // ---- per-chunk scale (one scale per 32-k block per row) ----
        const float2 sv = *(const float2*)&sm.sc[c][n0];
        acc[0] = fmaf(pd[0], sv.x, acc[0]);
        acc[1] = fmaf(pd[1], sv.y, acc[1]);
        acc[2] = fmaf(pd[2], sv.x, acc[2]);
        acc[3] = fmaf(pd[3], sv.y, acc[3]);
    }

    // ---- epilogue: write partials ----
    const int m    = lane >> 2;
    const int grow = growbase + n0;
    *(float2*)&g_part[ks][m][grow]     = make_float2(acc[0], acc[1]);
    *(float2*)&g_part[ks][m + 8][grow] = make_float2(acc[2], acc[3]);
}

// flat float4 reduce: 172 blocks x 256 threads == TOK * OUT_F / 4 exactly
__global__ void reduce16_kernel(const float* __restrict__ bias, float* __restrict__ out) {
    const int idx = blockIdx.x * 256 + threadIdx.x;     // 0..44031
    const int t   = idx / (OUT_F / 4);
    const int r4  = idx % (OUT_F / 4);
    const float4* p = (const float4*)&g_part[0][t][r4 * 4];
    const size_t stride = (size_t)TOK * OUT_F / 4;      // float4 stride between ks
    float4 a0 = p[0], a1 = p[stride], a2 = p[2 * stride], a3 = p[3 * stride];
#pragma unroll
    for (int ks = 4; ks < KSPLIT; ks += 4) {
        const float4 v0 = p[ks * stride],       v1 = p[(ks + 1) * stride];
        const float4 v2 = p[(ks + 2) * stride], v3 = p[(ks + 3) * stride];
        a0.x += v0.x; a0.y += v0.y; a0.z += v0.z; a0.w += v0.w;
        a1.x += v1.x; a1.y += v1.y; a1.z += v1.z; a1.w += v1.w;
        a2.x += v2.x; a2.y += v2.y; a2.z += v2.z; a2.w += v2.w;
        a3.x += v3.x; a3.y += v3.y; a3.z += v3.z; a3.w += v3.w;
    }
    const float4 b = *(const float4*)&bias[r4 * 4];
    float4 r;
    r.x = a0.x + a1.x + a2.x + a3.x + b.x;
    r.y = a0.y + a1.y + a2.y + a3.y + b.y;
    r.z = a0.z + a1.z + a2.z + a3.z + b.z;
    r.w = a0.w + a1.w + a2.w + a3.w + b.w;
    *(float4*)&out[(size_t)t * OUT_F + r4 * 4] = r;
}

extern "C" void kernel_launch(void* const* d_in, const int* in_sizes, int n_in,
                              void* d_out, int out_size) {
    const float* x      = (const float*)d_in[0];  // [16, 4096]
    const int*   wq     = (const int*)  d_in[1];  // [11008, 4096]
    const float* wscale = (const float*)d_in[2];  // [11008, 128]
    const float* bias   = (const float*)d_in[3];  // [11008]
    float* out = (float*)d_out;                   // [16, 11008]

    split_x_kernel<<<(TOK * IN_F / 2) / 256, 256>>>(x);
    q4_hmma4_kernel<<<dim3(NCTA_N, KSPLIT), THREADS>>>(wq, wscale);
    reduce16_kernel<<<(TOK * OUT_F / 4) / 256, 256>>>(bias, out);
}

// round 10
// speedup vs baseline: 2.0986x; 1.0335x over previous
#include <cuda_runtime.h>
#include <cuda_fp16.h>
#include <cstdint>

typedef unsigned int u32;

#define IN_F    4096
#define OUT_F   11008
#define TOK     16
#define THREADS 256
#define NTILE   64
#define NCTA_N  (OUT_F / NTILE)     // 172
#define KSPLIT  16
#define KPER    (IN_F / KSPLIT)     // 256
#define KCHUNK  32
#define NCHUNK  (KPER / KCHUNK)     // 8
#define RING    4

// dynamic smem layout (bytes)
#define SM_XT    0                  // [2 planes][16 m][32 units]*16B = 16384
#define SM_W     16384              // RING stages * 64 rows * 144B = 36864
#define SM_SC    53248              // [8 blk][64 row] f32 = 2048
#define SM_TOTAL 55296
#define WSTRIDE  144                // padded row: 36 int32 (2-way LDS worst case)
#define WSTAGE   (64 * WSTRIDE)     // 9216

__device__ float g_part[KSPLIT][TOK][OUT_F];   // 11.3 MB scratch

__device__ __forceinline__ u32 h2u(__half2 h) { return *reinterpret_cast<u32*>(&h); }
__device__ __forceinline__ __half2 u2h(u32 v) { return *reinterpret_cast<__half2*>(&v); }

__device__ __forceinline__ void mma16816(float* d, const u32* a, u32 b0, u32 b1) {
    asm volatile(
        "mma.sync.aligned.m16n8k16.row.col.f32.f16.f16.f32 "
        "{%0,%1,%2,%3}, {%4,%5,%6,%7}, {%8,%9}, {%0,%1,%2,%3};"
        : "+f"(d[0]), "+f"(d[1]), "+f"(d[2]), "+f"(d[3])
        : "r"(a[0]), "r"(a[1]), "r"(a[2]), "r"(a[3]), "r"(b0), "r"(b1));
}
__device__ __forceinline__ void mma16816_z(float* d, const u32* a, u32 b0, u32 b1) {
    asm volatile(
        "mma.sync.aligned.m16n8k16.row.col.f32.f16.f16.f32 "
        "{%0,%1,%2,%3}, {%4,%5,%6,%7}, {%8,%9}, {%10,%10,%10,%10};"
        : "=f"(d[0]), "=f"(d[1]), "=f"(d[2]), "=f"(d[3])
        : "r"(a[0]), "r"(a[1]), "r"(a[2]), "r"(a[3]), "r"(b0), "r"(b1), "f"(0.0f));
}
__device__ __forceinline__ void ldsm4(u32* r, u32 a) {
    asm volatile("ldmatrix.sync.aligned.m8n8.x4.shared.b16 {%0,%1,%2,%3}, [%4];"
                 : "=r"(r[0]), "=r"(r[1]), "=r"(r[2]), "=r"(r[3]) : "r"(a));
}
__device__ __forceinline__ void cp16(u32 dst, const void* src) {
    asm volatile("cp.async.cg.shared.global [%0], [%1], 16;\n" :: "r"(dst), "l"(src));
}

// raw nibble pair -> fp16 integers (q-8), exact: (0x6400|q) = 1024+q, minus 1032
__device__ __forceinline__ u32 qpair(int q0, int q1) {
    const u32 t = ((u32)q0 | ((u32)q1 << 16)) | 0x64006400u;
    return h2u(__hsub2(u2h(t), u2h(0x64086408u)));
}

__global__ void __launch_bounds__(THREADS, 4) q4_cp_kernel(
    const float* __restrict__ x,        // [16, 4096]
    const int*   __restrict__ wq,       // [11008, 4096]
    const float* __restrict__ wscale)   // [11008, 128]
{
    extern __shared__ char smem[];
    const u32 sb = (u32)__cvta_generic_to_shared(smem);
    const int tid  = threadIdx.x;
    const int warp = tid >> 5;
    const int lane = tid & 31;
    const int growbase = blockIdx.x * NTILE;
    const int ks    = blockIdx.y;
    const int kbase = ks * KPER;

    // ---- prologue: convert this CTA's whole x k-range to fp16 hi/lo tiles ----
    {
        const int m  = tid >> 4;            // token
        const int u0 = (tid & 15) * 2;      // 16B unit (8 halves = 8 k)
#pragma unroll
        for (int j = 0; j < 2; j++) {
            const int u = u0 + j;
            const float4 v0 = *(const float4*)(x + (size_t)m * IN_F + kbase + u * 8);
            const float4 v1 = *(const float4*)(x + (size_t)m * IN_F + kbase + u * 8 + 4);
            const __half2 h0 = __floats2half2_rn(v0.x, v0.y);
            const __half2 h1 = __floats2half2_rn(v0.z, v0.w);
            const __half2 h2 = __floats2half2_rn(v1.x, v1.y);
            const __half2 h3 = __floats2half2_rn(v1.z, v1.w);
            const float2 f0 = __half22float2(h0), f1 = __half22float2(h1);
            const float2 f2 = __half22float2(h2), f3 = __half22float2(h3);
            const __half2 l0 = __floats2half2_rn(v0.x - f0.x, v0.y - f0.y);
            const __half2 l1 = __floats2half2_rn(v0.z - f1.x, v0.w - f1.y);
            const __half2 l2 = __floats2half2_rn(v1.x - f2.x, v1.y - f2.y);
            const __half2 l3 = __floats2half2_rn(v1.z - f3.x, v1.w - f3.y);
            const int up = u ^ (m & 7);     // ldmatrix-phase conflict-free swizzle
            char* hb = smem + SM_XT + m * 512 + up * 16;
            *(uint4*)hb          = make_uint4(h2u(h0), h2u(h1), h2u(h2), h2u(h3));
            *(uint4*)(hb + 8192) = make_uint4(h2u(l0), h2u(l1), h2u(l2), h2u(l3));
        }
    }
    // ---- scales: [row][block] -> sc[block][row] ----
    for (int idx = tid; idx < NTILE * NCHUNK; idx += THREADS) {
        const int r = idx >> 3, b = idx & 7;
        ((float*)(smem + SM_SC))[b * 64 + r] =
            __ldg(wscale + (size_t)(growbase + r) * (IN_F / 32) + ks * NCHUNK + b);
    }

    // ---- w cp.async mapping: pieces tid, tid+256 -> rows tid>>3, +32 ----
    const int prow  = tid >> 3;
    const int punit = tid & 7;
    const int* wsrc = wq + (size_t)(growbase + prow) * IN_F + kbase + punit * 4;
    const u32  wdst = sb + SM_W + prow * WSTRIDE + punit * 16;

#pragma unroll
    for (int p = 0; p < RING - 1; p++) {    // stages 0..2
        cp16(wdst + p * WSTAGE, wsrc + p * KCHUNK);
        cp16(wdst + p * WSTAGE + 32 * WSTRIDE, wsrc + (size_t)32 * IN_F + p * KCHUNK);
        asm volatile("cp.async.commit_group;\n" ::: "memory");
    }

    float acc[4] = {0.f, 0.f, 0.f, 0.f};
    const int i  = lane & 7, jj = lane >> 3;
    const int am = i + ((jj & 1) << 3);                 // A fragment row (m)
    const int bn = (warp << 3) + (lane >> 2);           // B fragment row (n)
    const int n0 = (warp << 3) + ((lane & 3) << 1);     // D fragment n pair
    const u32 xt0 = sb + SM_XT;

#pragma unroll
    for (int c = 0; c < NCHUNK; c++) {
        asm volatile("cp.async.wait_group 2;\n" ::: "memory");   // stage c landed
        __syncthreads();                                         // publish to CTA

        // issue stage c+3 into the buffer freed at chunk c-1
        if (c + RING - 1 < NCHUNK) {
            const int p = c + RING - 1;
            cp16(wdst + (p & (RING - 1)) * WSTAGE, wsrc + p * KCHUNK);
            cp16(wdst + (p & (RING - 1)) * WSTAGE + 32 * WSTRIDE,
                 wsrc + (size_t)32 * IN_F + p * KCHUNK);
        }
        asm volatile("cp.async.commit_group;\n" ::: "memory");

        const u32 wst = sb + SM_W + (c & (RING - 1)) * WSTAGE;
        float pd[4];
#pragma unroll
        for (int s = 0; s < 2; s++) {
            // A fragments via ldmatrix (hi + lo planes)
            const int au   = c * 4 + 2 * s + (jj >> 1);
            const u32 aoff = am * 512 + ((au ^ (am & 7)) << 4);
            u32 ah[4], al[4];
            ldsm4(ah, xt0 + aoff);
            ldsm4(al, xt0 + 8192 + aoff);
            // B fragments straight from raw nibbles
            const u32 baddr = wst + bn * WSTRIDE + ((16 * s + 2 * (lane & 3)) << 2);
            const int2 q0 = *(const int2*)__cvta_shared_to_generic((size_t)baddr);
            const int2 q1 = *(const int2*)__cvta_shared_to_generic((size_t)(baddr + 32));
            const u32 b0 = qpair(q0.x, q0.y);
            const u32 b1 = qpair(q1.x, q1.y);
            if (s == 0) mma16816_z(pd, ah, b0, b1);
            else        mma16816  (pd, ah, b0, b1);
            mma16816(pd, al, b0, b1);
        }
        const float2 sv = *(const float2*)((float*)(smem + SM_SC) + c * 64 + n0);
        acc[0] = fmaf(pd[0], sv.x, acc[0]);
        acc[1] = fmaf(pd[1], sv.y, acc[1]);
        acc[2] = fmaf(pd[2], sv.x, acc[2]);
        acc[3] = fmaf(pd[3], sv.y, acc[3]);
    }

    // ---- epilogue: D rows m = lane>>2, +8; cols n0, n0+1 ----
    const int m    = lane >> 2;
    const int grow = growbase + n0;
    *(float2*)&g_part[ks][m][grow]     = make_float2(acc[0], acc[1]);
    *(float2*)&g_part[ks][m + 8][grow] = make_float2(acc[2], acc[3]);
}

// 344 x 128: each thread sums 16 independent partials (MLP 16) + bias
__global__ void reduce16_kernel(const float* __restrict__ bias, float* __restrict__ out) {
    const int idx = blockIdx.x * 128 + threadIdx.x;   // 0..44031
    const int t   = idx / (OUT_F / 4);
    const int r4  = idx % (OUT_F / 4);
    const float4* p = (const float4*)&g_part[0][t][r4 * 4];
    const size_t st = (size_t)TOK * OUT_F / 4;
    float4 v[KSPLIT];
#pragma unroll
    for (int k = 0; k < KSPLIT; k++) v[k] = p[k * st];
#pragma unroll
    for (int d = KSPLIT / 2; d > 0; d >>= 1)
#pragma unroll
        for (int k = 0; k < d; k++) {
            v[k].x += v[k + d].x; v[k].y += v[k + d].y;
            v[k].z += v[k + d].z; v[k].w += v[k + d].w;
        }
    const float4 b = *(const float4*)&bias[r4 * 4];
    float4 r;
    r.x = v[0].x + b.x; r.y = v[0].y + b.y;
    r.z = v[0].z + b.z; r.w = v[0].w + b.w;
    *(float4*)&out[(size_t)t * OUT_F + r4 * 4] = r;
}

extern "C" void kernel_launch(void* const* d_in, const int* in_sizes, int n_in,
                              void* d_out, int out_size) {
    const float* x      = (const float*)d_in[0];  // [16, 4096]
    const int*   wq     = (const int*)  d_in[1];  // [11008, 4096]
    const float* wscale = (const float*)d_in[2];  // [11008, 128]
    const float* bias   = (const float*)d_in[3];  // [11008]
    float* out = (float*)d_out;                   // [16, 11008]

    cudaFuncSetAttribute(q4_cp_kernel,
                         cudaFuncAttributeMaxDynamicSharedMemorySize, SM_TOTAL);
    q4_cp_kernel<<<dim3(NCTA_N, KSPLIT), THREADS, SM_TOTAL>>>(x, wq, wscale);
    reduce16_kernel<<<(TOK * OUT_F / 4) / 128, 128>>>(bias, out);
}

// round 13
// speedup vs baseline: 2.2521x; 1.0731x over previous
#include <cuda_runtime.h>
#include <cuda_fp16.h>
#include <cstdint>

typedef unsigned int u32;

#define IN_F    4096
#define OUT_F   11008
#define TOK     16
#define THREADS 256
#define NTILE   64
#define NCTA_N  (OUT_F / NTILE)     // 172
#define KSPLIT  16
#define KPER    (IN_F / KSPLIT)     // 256
#define KCHUNK  32
#define NCHUNK  (KPER / KCHUNK)     // 8
#define RING    4

// dynamic smem layout (bytes) — IDENTICAL to the passing R10 kernel
#define SM_XT    0                  // x tile region (hi plane used; 16 KB reserved)
#define SM_W     16384              // RING stages * 64 rows * 144B = 36864
#define SM_SC    53248              // [8 blk][64 row] f32 = 2048
#define SM_TOTAL 55296
#define WSTRIDE  144                // padded row: 36 int32
#define WSTAGE   (64 * WSTRIDE)     // 9216

__device__ float g_part[KSPLIT][TOK][OUT_F];   // 11.3 MB scratch

__device__ __forceinline__ u32 h2u(__half2 h) { return *reinterpret_cast<u32*>(&h); }
__device__ __forceinline__ __half2 u2h(u32 v) { return *reinterpret_cast<__half2*>(&v); }

__device__ __forceinline__ void mma16816(float* d, const u32* a, u32 b0, u32 b1) {
    asm volatile(
        "mma.sync.aligned.m16n8k16.row.col.f32.f16.f16.f32 "
        "{%0,%1,%2,%3}, {%4,%5,%6,%7}, {%8,%9}, {%0,%1,%2,%3};"
        : "+f"(d[0]), "+f"(d[1]), "+f"(d[2]), "+f"(d[3])
        : "r"(a[0]), "r"(a[1]), "r"(a[2]), "r"(a[3]), "r"(b0), "r"(b1));
}
__device__ __forceinline__ void mma16816_z(float* d, const u32* a, u32 b0, u32 b1) {
    asm volatile(
        "mma.sync.aligned.m16n8k16.row.col.f32.f16.f16.f32 "
        "{%0,%1,%2,%3}, {%4,%5,%6,%7}, {%8,%9}, {%10,%10,%10,%10};"
        : "=f"(d[0]), "=f"(d[1]), "=f"(d[2]), "=f"(d[3])
        : "r"(a[0]), "r"(a[1]), "r"(a[2]), "r"(a[3]), "r"(b0), "r"(b1), "f"(0.0f));
}
__device__ __forceinline__ void ldsm4(u32* r, u32 a) {
    asm volatile("ldmatrix.sync.aligned.m8n8.x4.shared.b16 {%0,%1,%2,%3}, [%4];"
                 : "=r"(r[0]), "=r"(r[1]), "=r"(r[2]), "=r"(r[3]) : "r"(a));
}
__device__ __forceinline__ void cp16(u32 dst, const void* src) {
    asm volatile("cp.async.cg.shared.global [%0], [%1], 16;\n" :: "r"(dst), "l"(src));
}

// raw nibble pair -> fp16 integers (q-8), exact: (0x6400|q) = 1024+q, minus 1032
__device__ __forceinline__ u32 qpair(int q0, int q1) {
    const u32 t = ((u32)q0 | ((u32)q1 << 16)) | 0x64006400u;
    return h2u(__hsub2(u2h(t), u2h(0x64086408u)));
}

__global__ void __launch_bounds__(THREADS, 4) q4_cp_kernel(
    const float* __restrict__ x,        // [16, 4096]
    const int*   __restrict__ wq,       // [11008, 4096]
    const float* __restrict__ wscale)   // [11008, 128]
{
    extern __shared__ char smem[];
    const u32 sb = (u32)__cvta_generic_to_shared(smem);
    const int tid  = threadIdx.x;
    const int warp = tid >> 5;
    const int lane = tid & 31;
    const int growbase = blockIdx.x * NTILE;
    const int ks    = blockIdx.y;
    const int kbase = ks * KPER;

    // ---- prologue: convert this CTA's x k-range to fp16 tile (hi plane only) ----
    {
        const int m  = tid >> 4;            // token
        const int u0 = (tid & 15) * 2;      // 16B unit (8 halves = 8 k)
#pragma unroll
        for (int j = 0; j < 2; j++) {
            const int u = u0 + j;
            const float4 v0 = *(const float4*)(x + (size_t)m * IN_F + kbase + u * 8);
            const float4 v1 = *(const float4*)(x + (size_t)m * IN_F + kbase + u * 8 + 4);
            const __half2 h0 = __floats2half2_rn(v0.x, v0.y);
            const __half2 h1 = __floats2half2_rn(v0.z, v0.w);
            const __half2 h2 = __floats2half2_rn(v1.x, v1.y);
            const __half2 h3 = __floats2half2_rn(v1.z, v1.w);
            const int up = u ^ (m & 7);     // ldmatrix-phase conflict-free swizzle
            *(uint4*)(smem + SM_XT + m * 512 + up * 16) =
                make_uint4(h2u(h0), h2u(h1), h2u(h2), h2u(h3));
        }
    }
    // ---- scales: [row][block] -> sc[block][row] ----
    for (int idx = tid; idx < NTILE * NCHUNK; idx += THREADS) {
        const int r = idx >> 3, b = idx & 7;
        ((float*)(smem + SM_SC))[b * 64 + r] =
            __ldg(wscale + (size_t)(growbase + r) * (IN_F / 32) + ks * NCHUNK + b);
    }

    // ---- w cp.async mapping: pieces tid, tid+256 -> rows tid>>3, +32 ----
    const int prow  = tid >> 3;
    const int punit = tid & 7;
    const int* wsrc = wq + (size_t)(growbase + prow) * IN_F + kbase + punit * 4;
    const u32  wdst = sb + SM_W + prow * WSTRIDE + punit * 16;

#pragma unroll
    for (int p = 0; p < RING - 1; p++) {    // stages 0..2
        cp16(wdst + p * WSTAGE, wsrc + p * KCHUNK);
        cp16(wdst + p * WSTAGE + 32 * WSTRIDE, wsrc + (size_t)32 * IN_F + p * KCHUNK);
        asm volatile("cp.async.commit_group;\n" ::: "memory");
    }

    float acc[4] = {0.f, 0.f, 0.f, 0.f};
    const int i  = lane & 7, jj = lane >> 3;
    const int am = i + ((jj & 1) << 3);                 // A fragment row (m)
    const int bn = (warp << 3) + (lane >> 2);           // B fragment row (n)
    const int n0 = (warp << 3) + ((lane & 3) << 1);     // D fragment n pair
    const u32 xt0 = sb + SM_XT;

#pragma unroll
    for (int c = 0; c < NCHUNK; c++) {
        asm volatile("cp.async.wait_group 2;\n" ::: "memory");   // stage c landed
        __syncthreads();                                         // publish to CTA

        // issue stage c+3 into the buffer freed at chunk c-1
        if (c + RING - 1 < NCHUNK) {
            const int p = c + RING - 1;
            cp16(wdst + (p & (RING - 1)) * WSTAGE, wsrc + p * KCHUNK);
            cp16(wdst + (p & (RING - 1)) * WSTAGE + 32 * WSTRIDE,
                 wsrc + (size_t)32 * IN_F + p * KCHUNK);
        }
        asm volatile("cp.async.commit_group;\n" ::: "memory");

        const u32 wst = sb + SM_W + (c & (RING - 1)) * WSTAGE;
        float pd[4];
#pragma unroll
        for (int s = 0; s < 2; s++) {
            // A fragment via ldmatrix (hi plane only)
            const int au   = c * 4 + 2 * s + (jj >> 1);
            const u32 aoff = am * 512 + ((au ^ (am & 7)) << 4);
            u32 ah[4];
            ldsm4(ah, xt0 + aoff);
            // B fragment straight from raw nibbles (generic LDS, proven path)
            const u32 baddr = wst + bn * WSTRIDE + ((16 * s + 2 * (lane & 3)) << 2);
            const int2 q0 = *(const int2*)__cvta_shared_to_generic((size_t)baddr);
            const int2 q1 = *(const int2*)__cvta_shared_to_generic((size_t)(baddr + 32));
            const u32 b0 = qpair(q0.x, q0.y);
            const u32 b1 = qpair(q1.x, q1.y);
            if (s == 0) mma16816_z(pd, ah, b0, b1);
            else        mma16816  (pd, ah, b0, b1);
        }
        const float2 sv = *(const float2*)((float*)(smem + SM_SC) + c * 64 + n0);
        acc[0] = fmaf(pd[0], sv.x, acc[0]);
        acc[1] = fmaf(pd[1], sv.y, acc[1]);
        acc[2] = fmaf(pd[2], sv.x, acc[2]);
        acc[3] = fmaf(pd[3], sv.y, acc[3]);
    }

    // ---- epilogue: D rows m = lane>>2, +8; cols n0, n0+1 ----
    const int m    = lane >> 2;
    const int grow = growbase + n0;
    *(float2*)&g_part[ks][m][grow]     = make_float2(acc[0], acc[1]);
    *(float2*)&g_part[ks][m + 8][grow] = make_float2(acc[2], acc[3]);
}

// 344 blocks x 256: one float2 per thread, 16 independent loads, tree sum
__global__ void reduce16c_kernel(const float* __restrict__ bias, float* __restrict__ out) {
    const int idx = blockIdx.x * 256 + threadIdx.x;   // 0..88063
    const int t   = idx / (OUT_F / 2);
    const int r2  = idx % (OUT_F / 2);
    const float2* p = (const float2*)&g_part[0][t][r2 * 2];
    const size_t st = (size_t)TOK * OUT_F / 2;        // float2 stride between ks
    float2 v[KSPLIT];
#pragma unroll
    for (int k = 0; k < KSPLIT; k++) v[k] = p[k * st];
#pragma unroll
    for (int d = KSPLIT / 2; d > 0; d >>= 1)
#pragma unroll
        for (int k = 0; k < d; k++) { v[k].x += v[k + d].x; v[k].y += v[k + d].y; }
    const float2 b = *(const float2*)&bias[r2 * 2];
    float2 r;
    r.x = v[0].x + b.x;
    r.y = v[0].y + b.y;
    *(float2*)&out[(size_t)t * OUT_F + r2 * 2] = r;
}

extern "C" void kernel_launch(void* const* d_in, const int* in_sizes, int n_in,
                              void* d_out, int out_size) {
    const float* x      = (const float*)d_in[0];  // [16, 4096]
    const int*   wq     = (const int*)  d_in[1];  // [11008, 4096]
    const float* wscale = (const float*)d_in[2];  // [11008, 128]
    const float* bias   = (const float*)d_in[3];  // [11008]
    float* out = (float*)d_out;                   // [16, 11008]

    cudaFuncSetAttribute(q4_cp_kernel,
                         cudaFuncAttributeMaxDynamicSharedMemorySize, SM_TOTAL);
    q4_cp_kernel<<<dim3(NCTA_N, KSPLIT), THREADS, SM_TOTAL>>>(x, wq, wscale);
    reduce16c_kernel<<<(TOK * OUT_F / 2) / 256, 256>>>(bias, out);
}

// round 14
// speedup vs baseline: 2.3611x; 1.0484x over previous
#include <cuda_runtime.h>
#include <cuda_fp16.h>
#include <cstdint>

typedef unsigned int u32;

#define IN_F    4096
#define OUT_F   11008
#define TOK     16
#define THREADS 256
#define NTILE   64
#define NCTA_N  (OUT_F / NTILE)     // 172
#define KSPLIT  16
#define KPER    (IN_F / KSPLIT)     // 256
#define KCHUNK  64
#define NCHUNK  (KPER / KCHUNK)     // 4
#define RING    3

// dynamic smem layout (bytes)
#define SM_XT    0                  // x tile: [16 m][32 units]*16B = 8192
#define SM_W     8192               // RING * 64 rows * 288B = 55296
#define SM_SC    63488              // [8 blk][64 row] f32 = 2048
#define SM_TOTAL 65536
#define WSTRIDE  288                // 72 words == 8 mod 32 -> conflict-free B LDS.64
#define WSTAGE   (64 * WSTRIDE)     // 18432

__device__ float g_part[KSPLIT][TOK][OUT_F];   // 11.3 MB scratch

__device__ __forceinline__ u32 h2u(__half2 h) { return *reinterpret_cast<u32*>(&h); }
__device__ __forceinline__ __half2 u2h(u32 v) { return *reinterpret_cast<__half2*>(&v); }

__device__ __forceinline__ void mma16816(float* d, const u32* a, u32 b0, u32 b1) {
    asm volatile(
        "mma.sync.aligned.m16n8k16.row.col.f32.f16.f16.f32 "
        "{%0,%1,%2,%3}, {%4,%5,%6,%7}, {%8,%9}, {%0,%1,%2,%3};"
        : "+f"(d[0]), "+f"(d[1]), "+f"(d[2]), "+f"(d[3])
        : "r"(a[0]), "r"(a[1]), "r"(a[2]), "r"(a[3]), "r"(b0), "r"(b1));
}
__device__ __forceinline__ void mma16816_z(float* d, const u32* a, u32 b0, u32 b1) {
    asm volatile(
        "mma.sync.aligned.m16n8k16.row.col.f32.f16.f16.f32 "
        "{%0,%1,%2,%3}, {%4,%5,%6,%7}, {%8,%9}, {%10,%10,%10,%10};"
        : "=f"(d[0]), "=f"(d[1]), "=f"(d[2]), "=f"(d[3])
        : "r"(a[0]), "r"(a[1]), "r"(a[2]), "r"(a[3]), "r"(b0), "r"(b1), "f"(0.0f));
}
__device__ __forceinline__ void ldsm4(u32* r, u32 a) {
    asm volatile("ldmatrix.sync.aligned.m8n8.x4.shared.b16 {%0,%1,%2,%3}, [%4];"
                 : "=r"(r[0]), "=r"(r[1]), "=r"(r[2]), "=r"(r[3]) : "r"(a));
}
__device__ __forceinline__ void cp16(u32 dst, const void* src) {
    asm volatile("cp.async.cg.shared.global [%0], [%1], 16;\n" :: "r"(dst), "l"(src));
}

// raw nibble pair -> fp16 integers (q-8), exact: (0x6400|q) = 1024+q, minus 1032
__device__ __forceinline__ u32 qpair(int q0, int q1) {
    const u32 t = ((u32)q0 | ((u32)q1 << 16)) | 0x64006400u;
    return h2u(__hsub2(u2h(t), u2h(0x64086408u)));
}

__global__ void __launch_bounds__(THREADS, 3) q4_cp_kernel(
    const float* __restrict__ x,        // [16, 4096]
    const int*   __restrict__ wq,       // [11008, 4096]
    const float* __restrict__ wscale)   // [11008, 128]
{
    extern __shared__ char smem[];
    const u32 sb = (u32)__cvta_generic_to_shared(smem);
    const int tid  = threadIdx.x;
    const int warp = tid >> 5;
    const int lane = tid & 31;
    const int growbase = blockIdx.x * NTILE;
    const int ks    = blockIdx.y;
    const int kbase = ks * KPER;

    // ---- prologue: convert this CTA's x k-range to fp16 tile ----
    {
        const int m  = tid >> 4;            // token
        const int u0 = (tid & 15) * 2;      // 16B unit (8 halves = 8 k)
#pragma unroll
        for (int j = 0; j < 2; j++) {
            const int u = u0 + j;
            const float4 v0 = *(const float4*)(x + (size_t)m * IN_F + kbase + u * 8);
            const float4 v1 = *(const float4*)(x + (size_t)m * IN_F + kbase + u * 8 + 4);
            const __half2 h0 = __floats2half2_rn(v0.x, v0.y);
            const __half2 h1 = __floats2half2_rn(v0.z, v0.w);
            const __half2 h2 = __floats2half2_rn(v1.x, v1.y);
            const __half2 h3 = __floats2half2_rn(v1.z, v1.w);
            const int up = u ^ (m & 7);     // ldmatrix-phase conflict-free swizzle
            *(uint4*)(smem + SM_XT + m * 512 + up * 16) =
                make_uint4(h2u(h0), h2u(h1), h2u(h2), h2u(h3));
        }
    }
    // ---- scales: [row][block] -> sc[block][row] ----
    for (int idx = tid; idx < NTILE * 8; idx += THREADS) {
        const int r = idx >> 3, b = idx & 7;
        ((float*)(smem + SM_SC))[b * 64 + r] =
            __ldg(wscale + (size_t)(growbase + r) * (IN_F / 32) + ks * 8 + b);
    }

    // ---- w cp.async mapping: row = tid>>2, 4 units of 16B per thread ----
    const int prow = tid >> 2;
    const int pcol = tid & 3;
    const int* wsrc = wq + (size_t)(growbase + prow) * IN_F + kbase + pcol * 4;
    const u32  wdst = sb + SM_W + prow * WSTRIDE + pcol * 16;

#pragma unroll
    for (int p = 0; p < RING - 1; p++) {    // stages 0,1
#pragma unroll
        for (int j = 0; j < 4; j++)
            cp16(wdst + p * WSTAGE + j * 64, wsrc + p * KCHUNK + j * 16);
        asm volatile("cp.async.commit_group;\n" ::: "memory");
    }

    float acc[4] = {0.f, 0.f, 0.f, 0.f};
    const int i  = lane & 7, jj = lane >> 3;
    const int am = i + ((jj & 1) << 3);                 // A fragment row (m)
    const int bn = (warp << 3) + (lane >> 2);           // B fragment row (n)
    const int n0 = (warp << 3) + ((lane & 3) << 1);     // D fragment n pair
    const u32 xt0 = sb + SM_XT;

#pragma unroll
    for (int c = 0; c < NCHUNK; c++) {
        asm volatile("cp.async.wait_group 1;\n" ::: "memory");   // stage c landed
        __syncthreads();                                         // publish to CTA

        // issue stage c+2 into the slot consumed at chunk c-1
        if (c + RING - 1 < NCHUNK) {
            const int p = c + RING - 1;
            const u32 d = wdst + (u32)((p % RING) * WSTAGE);
#pragma unroll
            for (int j = 0; j < 4; j++)
                cp16(d + j * 64, wsrc + p * KCHUNK + j * 16);
        }
        asm volatile("cp.async.commit_group;\n" ::: "memory");

        const u32 wst = sb + SM_W + (u32)((c % RING) * WSTAGE);
        float pd0[4], pd1[4];
#pragma unroll
        for (int s = 0; s < 4; s++) {
            // A fragment via ldmatrix
            const int au   = c * 8 + 2 * s + (jj >> 1);
            const u32 aoff = am * 512 + ((au ^ (am & 7)) << 4);
            u32 ah[4];
            ldsm4(ah, xt0 + aoff);
            // B fragment straight from raw nibbles (conflict-free stride 288)
            const u32 baddr = wst + bn * WSTRIDE + ((16 * s + 2 * (lane & 3)) << 2);
            const int2 q0 = *(const int2*)__cvta_shared_to_generic((size_t)baddr);
            const int2 q1 = *(const int2*)__cvta_shared_to_generic((size_t)(baddr + 32));
            const u32 b0 = qpair(q0.x, q0.y);
            const u32 b1 = qpair(q1.x, q1.y);
            float* pd = (s < 2) ? pd0 : pd1;
            if (s == 0 || s == 2) mma16816_z(pd, ah, b0, b1);
            else                  mma16816  (pd, ah, b0, b1);
        }
        // per-32k-block scales: blocks 2c (k 0-31) and 2c+1 (k 32-63)
        const float* scp = (const float*)(smem + SM_SC);
        const float2 sv0 = *(const float2*)(scp + (2 * c)     * 64 + n0);
        const float2 sv1 = *(const float2*)(scp + (2 * c + 1) * 64 + n0);
        acc[0] = fmaf(pd0[0], sv0.x, acc[0]); acc[0] = fmaf(pd1[0], sv1.x, acc[0]);
        acc[1] = fmaf(pd0[1], sv0.y, acc[1]); acc[1] = fmaf(pd1[1], sv1.y, acc[1]);
        acc[2] = fmaf(pd0[2], sv0.x, acc[2]); acc[2] = fmaf(pd1[2], sv1.x, acc[2]);
        acc[3] = fmaf(pd0[3], sv0.y, acc[3]); acc[3] = fmaf(pd1[3], sv1.y, acc[3]);
    }

    // ---- epilogue: D rows m = lane>>2, +8; cols n0, n0+1 ----
    const int m    = lane >> 2;
    const int grow = growbase + n0;
    *(float2*)&g_part[ks][m][grow]     = make_float2(acc[0], acc[1]);
    *(float2*)&g_part[ks][m + 8][grow] = make_float2(acc[2], acc[3]);
}

// 344 blocks x 256: one float2 per thread, 16 independent loads, tree sum
__global__ void reduce16c_kernel(const float* __restrict__ bias, float* __restrict__ out) {
    const int idx = blockIdx.x * 256 + threadIdx.x;   // 0..88063
    const int t   = idx / (OUT_F / 2);
    const int r2  = idx % (OUT_F / 2);
    const float2* p = (const float2*)&g_part[0][t][r2 * 2];
    const size_t st = (size_t)TOK * OUT_F / 2;        // float2 stride between ks
    float2 v[KSPLIT];
#pragma unroll
    for (int k = 0; k < KSPLIT; k++) v[k] = p[k * st];
#pragma unroll
    for (int d = KSPLIT / 2; d > 0; d >>= 1)
#pragma unroll
        for (int k = 0; k < d; k++) { v[k].x += v[k + d].x; v[k].y += v[k + d].y; }
    const float2 b = *(const float2*)&bias[r2 * 2];
    float2 r;
    r.x = v[0].x + b.x;
    r.y = v[0].y + b.y;
    *(float2*)&out[(size_t)t * OUT_F + r2 * 2] = r;
}

extern "C" void kernel_launch(void* const* d_in, const int* in_sizes, int n_in,
                              void* d_out, int out_size) {
    const float* x      = (const float*)d_in[0];  // [16, 4096]
    const int*   wq     = (const int*)  d_in[1];  // [11008, 4096]
    const float* wscale = (const float*)d_in[2];  // [11008, 128]
    const float* bias   = (const float*)d_in[3];  // [11008]
    float* out = (float*)d_out;                   // [16, 11008]

    cudaFuncSetAttribute(q4_cp_kernel,
                         cudaFuncAttributeMaxDynamicSharedMemorySize, SM_TOTAL);
    q4_cp_kernel<<<dim3(NCTA_N, KSPLIT), THREADS, SM_TOTAL>>>(x, wq, wscale);
    reduce16c_kernel<<<(TOK * OUT_F / 2) / 256, 256>>>(bias, out);
}

// round 15
// speedup vs baseline: 2.4518x; 1.0384x over previous
#include <cuda_runtime.h>
#include <cuda_fp16.h>
#include <cstdint>

typedef unsigned int u32;

#define IN_F    4096
#define OUT_F   11008
#define TOK     16
#define THREADS 256
#define NTILE   64
#define NCTA_N  (OUT_F / NTILE)     // 172
#define KSPLIT  16
#define KPER    (IN_F / KSPLIT)     // 256
#define KCHUNK  64
#define NCHUNK  (KPER / KCHUNK)     // 4
#define RING    3

// dynamic smem layout (bytes)
#define SM_XT    0                  // x tile: [16 m][32 units]*16B = 8192
#define SM_W     8192               // RING * 64 rows * 288B = 55296
#define SM_SC    63488              // [8 blk][64 row] f32 = 2048
#define SM_TOTAL 65536
#define WSTRIDE  288                // 72 words == 8 mod 32 -> conflict-free B LDS.64
#define WSTAGE   (64 * WSTRIDE)     // 18432

__device__ float g_part[KSPLIT][TOK][OUT_F];   // 11.3 MB scratch

__device__ __forceinline__ u32 h2u(__half2 h) { return *reinterpret_cast<u32*>(&h); }
__device__ __forceinline__ __half2 u2h(u32 v) { return *reinterpret_cast<__half2*>(&v); }

__device__ __forceinline__ void mma16816(float* d, const u32* a, u32 b0, u32 b1) {
    asm volatile(
        "mma.sync.aligned.m16n8k16.row.col.f32.f16.f16.f32 "
        "{%0,%1,%2,%3}, {%4,%5,%6,%7}, {%8,%9}, {%0,%1,%2,%3};"
        : "+f"(d[0]), "+f"(d[1]), "+f"(d[2]), "+f"(d[3])
        : "r"(a[0]), "r"(a[1]), "r"(a[2]), "r"(a[3]), "r"(b0), "r"(b1));
}
__device__ __forceinline__ void mma16816_z(float* d, const u32* a, u32 b0, u32 b1) {
    asm volatile(
        "mma.sync.aligned.m16n8k16.row.col.f32.f16.f16.f32 "
        "{%0,%1,%2,%3}, {%4,%5,%6,%7}, {%8,%9}, {%10,%10,%10,%10};"
        : "=f"(d[0]), "=f"(d[1]), "=f"(d[2]), "=f"(d[3])
        : "r"(a[0]), "r"(a[1]), "r"(a[2]), "r"(a[3]), "r"(b0), "r"(b1), "f"(0.0f));
}
__device__ __forceinline__ void ldsm4(u32* r, u32 a) {
    asm volatile("ldmatrix.sync.aligned.m8n8.x4.shared.b16 {%0,%1,%2,%3}, [%4];"
                 : "=r"(r[0]), "=r"(r[1]), "=r"(r[2]), "=r"(r[3]) : "r"(a));
}
__device__ __forceinline__ void cp16(u32 dst, const void* src) {
    asm volatile("cp.async.cg.shared.global [%0], [%1], 16;\n" :: "r"(dst), "l"(src));
}

// raw nibble pair -> fp16 integers (q-8), exact: (0x6400|q) = 1024+q, minus 1032
__device__ __forceinline__ u32 qpair(int q0, int q1) {
    const u32 t = ((u32)q0 | ((u32)q1 << 16)) | 0x64006400u;
    return h2u(__hsub2(u2h(t), u2h(0x64086408u)));
}

__global__ void __launch_bounds__(THREADS, 3) q4_cp_kernel(
    const float* __restrict__ x,        // [16, 4096]
    const int*   __restrict__ wq,       // [11008, 4096]
    const float* __restrict__ wscale)   // [11008, 128]
{
    extern __shared__ char smem[];
    const u32 sb = (u32)__cvta_generic_to_shared(smem);
    const int tid  = threadIdx.x;
    const int warp = tid >> 5;
    const int lane = tid & 31;
    const int growbase = blockIdx.x * NTILE;
    const int ks    = blockIdx.y;
    const int kbase = ks * KPER;

    // ---- w cp.async prologue FIRST: get DRAM moving before x conversion ----
    const int prow = tid >> 2;
    const int pcol = tid & 3;
    const int* wsrc = wq + (size_t)(growbase + prow) * IN_F + kbase + pcol * 4;
    const u32  wdst = sb + SM_W + prow * WSTRIDE + pcol * 16;

#pragma unroll
    for (int p = 0; p < RING - 1; p++) {    // stages 0,1
#pragma unroll
        for (int j = 0; j < 4; j++)
            cp16(wdst + p * WSTAGE + j * 64, wsrc + p * KCHUNK + j * 16);
        asm volatile("cp.async.commit_group;\n" ::: "memory");
    }

    // ---- convert this CTA's x k-range to fp16 tile (overlaps W stage DMAs) ----
    {
        const int m  = tid >> 4;            // token
        const int u0 = (tid & 15) * 2;      // 16B unit (8 halves = 8 k)
#pragma unroll
        for (int j = 0; j < 2; j++) {
            const int u = u0 + j;
            const float4 v0 = *(const float4*)(x + (size_t)m * IN_F + kbase + u * 8);
            const float4 v1 = *(const float4*)(x + (size_t)m * IN_F + kbase + u * 8 + 4);
            const __half2 h0 = __floats2half2_rn(v0.x, v0.y);
            const __half2 h1 = __floats2half2_rn(v0.z, v0.w);
            const __half2 h2 = __floats2half2_rn(v1.x, v1.y);
            const __half2 h3 = __floats2half2_rn(v1.z, v1.w);
            const int up = u ^ (m & 7);     // ldmatrix-phase conflict-free swizzle
            *(uint4*)(smem + SM_XT + m * 512 + up * 16) =
                make_uint4(h2u(h0), h2u(h1), h2u(h2), h2u(h3));
        }
    }
    // ---- scales: [row][block] -> sc[block][row] ----
    for (int idx = tid; idx < NTILE * 8; idx += THREADS) {
        const int r = idx >> 3, b = idx & 7;
        ((float*)(smem + SM_SC))[b * 64 + r] =
            __ldg(wscale + (size_t)(growbase + r) * (IN_F / 32) + ks * 8 + b);
    }

    float acc[4] = {0.f, 0.f, 0.f, 0.f};
    const int i  = lane & 7, jj = lane >> 3;
    const int am = i + ((jj & 1) << 3);                 // A fragment row (m)
    const int bn = (warp << 3) + (lane >> 2);           // B fragment row (n)
    const int n0 = (warp << 3) + ((lane & 3) << 1);     // D fragment n pair
    const u32 xt0 = sb + SM_XT;

#pragma unroll
    for (int c = 0; c < NCHUNK; c++) {
        asm volatile("cp.async.wait_group 1;\n" ::: "memory");   // stage c landed
        __syncthreads();                                         // publish to CTA

        // issue stage c+2 into the slot consumed at chunk c-1
        if (c + RING - 1 < NCHUNK) {
            const int p = c + RING - 1;
            const u32 d = wdst + (u32)((p % RING) * WSTAGE);
#pragma unroll
            for (int j = 0; j < 4; j++)
                cp16(d + j * 64, wsrc + p * KCHUNK + j * 16);
        }
        asm volatile("cp.async.commit_group;\n" ::: "memory");

        const u32 wst = sb + SM_W + (u32)((c % RING) * WSTAGE);
        float pd0[4], pd1[4];
#pragma unroll
        for (int s = 0; s < 4; s++) {
            // A fragment via ldmatrix
            const int au   = c * 8 + 2 * s + (jj >> 1);
            const u32 aoff = am * 512 + ((au ^ (am & 7)) << 4);
            u32 ah[4];
            ldsm4(ah, xt0 + aoff);
            // B fragment straight from raw nibbles (conflict-free stride 288)
            const u32 baddr = wst + bn * WSTRIDE + ((16 * s + 2 * (lane & 3)) << 2);
            const int2 q0 = *(const int2*)__cvta_shared_to_generic((size_t)baddr);
            const int2 q1 = *(const int2*)__cvta_shared_to_generic((size_t)(baddr + 32));
            const u32 b0 = qpair(q0.x, q0.y);
            const u32 b1 = qpair(q1.x, q1.y);
            float* pd = (s < 2) ? pd0 : pd1;
            if (s == 0 || s == 2) mma16816_z(pd, ah, b0, b1);
            else                  mma16816  (pd, ah, b0, b1);
        }
        // per-32k-block scales: blocks 2c (k 0-31) and 2c+1 (k 32-63)
        const float* scp = (const float*)(smem + SM_SC);
        const float2 sv0 = *(const float2*)(scp + (2 * c)     * 64 + n0);
        const float2 sv1 = *(const float2*)(scp + (2 * c + 1) * 64 + n0);
        acc[0] = fmaf(pd0[0], sv0.x, acc[0]); acc[0] = fmaf(pd1[0], sv1.x, acc[0]);
        acc[1] = fmaf(pd0[1], sv0.y, acc[1]); acc[1] = fmaf(pd1[1], sv1.y, acc[1]);
        acc[2] = fmaf(pd0[2], sv0.x, acc[2]); acc[2] = fmaf(pd1[2], sv1.x, acc[2]);
        acc[3] = fmaf(pd0[3], sv0.y, acc[3]); acc[3] = fmaf(pd1[3], sv1.y, acc[3]);
    }

    // ---- epilogue: D rows m = lane>>2, +8; cols n0, n0+1 ----
    const int m    = lane >> 2;
    const int grow = growbase + n0;
    *(float2*)&g_part[ks][m][grow]     = make_float2(acc[0], acc[1]);
    *(float2*)&g_part[ks][m + 8][grow] = make_float2(acc[2], acc[3]);
}

// pair-split reduce: adjacent lanes each sum 8 ks as float4 (8 indep LDG.128),
// combine via shfl, even lane stores. 344 blocks x 256 = 2 threads per float4 out.
__global__ void __launch_bounds__(256) reduce16d_kernel(
    const float* __restrict__ bias, float* __restrict__ out)
{
    const int gid  = blockIdx.x * 256 + threadIdx.x;   // 0..88063
    const int o4   = gid >> 1;                         // float4 output index
    const int half = gid & 1;                          // ks half: 0 -> 0-7, 1 -> 8-15
    const int t    = o4 / (OUT_F / 4);
    const int r4   = o4 % (OUT_F / 4);
    const float4* p = (const float4*)&g_part[half * 8][t][r4 * 4];
    const size_t st = (size_t)TOK * OUT_F / 4;         // float4 stride between ks
    float4 v[8];
#pragma unroll
    for (int k = 0; k < 8; k++) v[k] = p[k * st];
#pragma unroll
    for (int d = 4; d > 0; d >>= 1)
#pragma unroll
        for (int k = 0; k < d; k++) {
            v[k].x += v[k + d].x; v[k].y += v[k + d].y;
            v[k].z += v[k + d].z; v[k].w += v[k + d].w;
        }
    // combine the two ks-halves across the lane pair
    v[0].x += __shfl_xor_sync(0xffffffffu, v[0].x, 1);
    v[0].y += __shfl_xor_sync(0xffffffffu, v[0].y, 1);
    v[0].z += __shfl_xor_sync(0xffffffffu, v[0].z, 1);
    v[0].w += __shfl_xor_sync(0xffffffffu, v[0].w, 1);
    if (half == 0) {
        const float4 b = *(const float4*)&bias[r4 * 4];
        float4 r;
        r.x = v[0].x + b.x; r.y = v[0].y + b.y;
        r.z = v[0].z + b.z; r.w = v[0].w + b.w;
        *(float4*)&out[(size_t)t * OUT_F + r4 * 4] = r;
    }
}

extern "C" void kernel_launch(void* const* d_in, const int* in_sizes, int n_in,
                              void* d_out, int out_size) {
    const float* x      = (const float*)d_in[0];  // [16, 4096]
    const int*   wq     = (const int*)  d_in[1];  // [11008, 4096]
    const float* wscale = (const float*)d_in[2];  // [11008, 128]
    const float* bias   = (const float*)d_in[3];  // [11008]
    float* out = (float*)d_out;                   // [16, 11008]

    cudaFuncSetAttribute(q4_cp_kernel,
                         cudaFuncAttributeMaxDynamicSharedMemorySize, SM_TOTAL);
    q4_cp_kernel<<<dim3(NCTA_N, KSPLIT), THREADS, SM_TOTAL>>>(x, wq, wscale);
    reduce16d_kernel<<<(TOK * OUT_F / 2) / 256, 256>>>(bias, out);
}

// round 16
// speedup vs baseline: 2.5854x; 1.0545x over previous
#include <cuda_runtime.h>
#include <cuda_fp16.h>
#include <cstdint>

typedef unsigned int u32;

#define IN_F    4096
#define OUT_F   11008
#define TOK     16
#define THREADS 256
#define NTILE   64
#define NCTA_N  (OUT_F / NTILE)     // 172
#define KSPLIT  16
#define KPER    (IN_F / KSPLIT)     // 256
#define KCHUNK  64
#define NCHUNK  (KPER / KCHUNK)     // 4
#define RING    3

// dynamic smem layout (bytes)
#define SM_XT    0                  // x tile: [16 m][32 units]*16B = 8192
#define SM_W     8192               // RING * 64 rows * 288B = 55296
#define SM_SC    63488              // [8 blk][64 row] f32 = 2048
#define SM_TOTAL 65536
#define WSTRIDE  288                // 72 words == 8 mod 32 -> conflict-free B LDS.64
#define WSTAGE   (64 * WSTRIDE)     // 18432

__device__ __forceinline__ u32 h2u(__half2 h) { return *reinterpret_cast<u32*>(&h); }
__device__ __forceinline__ __half2 u2h(u32 v) { return *reinterpret_cast<__half2*>(&v); }

__device__ __forceinline__ void mma16816(float* d, const u32* a, u32 b0, u32 b1) {
    asm volatile(
        "mma.sync.aligned.m16n8k16.row.col.f32.f16.f16.f32 "
        "{%0,%1,%2,%3}, {%4,%5,%6,%7}, {%8,%9}, {%0,%1,%2,%3};"
        : "+f"(d[0]), "+f"(d[1]), "+f"(d[2]), "+f"(d[3])
        : "r"(a[0]), "r"(a[1]), "r"(a[2]), "r"(a[3]), "r"(b0), "r"(b1));
}
__device__ __forceinline__ void mma16816_z(float* d, const u32* a, u32 b0, u32 b1) {
    asm volatile(
        "mma.sync.aligned.m16n8k16.row.col.f32.f16.f16.f32 "
        "{%0,%1,%2,%3}, {%4,%5,%6,%7}, {%8,%9}, {%10,%10,%10,%10};"
        : "=f"(d[0]), "=f"(d[1]), "=f"(d[2]), "=f"(d[3])
        : "r"(a[0]), "r"(a[1]), "r"(a[2]), "r"(a[3]), "r"(b0), "r"(b1), "f"(0.0f));
}
__device__ __forceinline__ void ldsm4(u32* r, u32 a) {
    asm volatile("ldmatrix.sync.aligned.m8n8.x4.shared.b16 {%0,%1,%2,%3}, [%4];"
                 : "=r"(r[0]), "=r"(r[1]), "=r"(r[2]), "=r"(r[3]) : "r"(a));
}
__device__ __forceinline__ void cp16(u32 dst, const void* src) {
    asm volatile("cp.async.cg.shared.global [%0], [%1], 16;\n" :: "r"(dst), "l"(src));
}

// raw nibble pair -> fp16 integers (q-8), exact: (0x6400|q) = 1024+q, minus 1032
__device__ __forceinline__ u32 qpair(int q0, int q1) {
    const u32 t = ((u32)q0 | ((u32)q1 << 16)) | 0x64006400u;
    return h2u(__hsub2(u2h(t), u2h(0x64086408u)));
}

// out[t][r] = bias[r] before the main kernel accumulates into it
__global__ void bias_init_kernel(const float* __restrict__ bias,
                                 float* __restrict__ out) {
    const int idx = blockIdx.x * 256 + threadIdx.x;   // 0..44031 float4s
    const int r4  = idx % (OUT_F / 4);
    ((float4*)out)[idx] = *(const float4*)&bias[r4 * 4];
}

__global__ void __launch_bounds__(THREADS, 3) q4_cp_kernel(
    const float* __restrict__ x,        // [16, 4096]
    const int*   __restrict__ wq,       // [11008, 4096]
    const float* __restrict__ wscale,   // [11008, 128]
    float*       __restrict__ out)      // [16, 11008], preloaded with bias
{
    extern __shared__ char smem[];
    const u32 sb = (u32)__cvta_generic_to_shared(smem);
    const int tid  = threadIdx.x;
    const int warp = tid >> 5;
    const int lane = tid & 31;
    const int growbase = blockIdx.x * NTILE;
    const int ks    = blockIdx.y;
    const int kbase = ks * KPER;

    // ---- w cp.async prologue FIRST: get DRAM moving before x conversion ----
    const int prow = tid >> 2;
    const int pcol = tid & 3;
    const int* wsrc = wq + (size_t)(growbase + prow) * IN_F + kbase + pcol * 4;
    const u32  wdst = sb + SM_W + prow * WSTRIDE + pcol * 16;

#pragma unroll
    for (int p = 0; p < RING - 1; p++) {    // stages 0,1
#pragma unroll
        for (int j = 0; j < 4; j++)
            cp16(wdst + p * WSTAGE + j * 64, wsrc + p * KCHUNK + j * 16);
        asm volatile("cp.async.commit_group;\n" ::: "memory");
    }

    // ---- convert this CTA's x k-range to fp16 tile (overlaps W stage DMAs) ----
    {
        const int m  = tid >> 4;            // token
        const int u0 = (tid & 15) * 2;      // 16B unit (8 halves = 8 k)
#pragma unroll
        for (int j = 0; j < 2; j++) {
            const int u = u0 + j;
            const float4 v0 = *(const float4*)(x + (size_t)m * IN_F + kbase + u * 8);
            const float4 v1 = *(const float4*)(x + (size_t)m * IN_F + kbase + u * 8 + 4);
            const __half2 h0 = __floats2half2_rn(v0.x, v0.y);
            const __half2 h1 = __floats2half2_rn(v0.z, v0.w);
            const __half2 h2 = __floats2half2_rn(v1.x, v1.y);
            const __half2 h3 = __floats2half2_rn(v1.z, v1.w);
            const int up = u ^ (m & 7);     // ldmatrix-phase conflict-free swizzle
            *(uint4*)(smem + SM_XT + m * 512 + up * 16) =
                make_uint4(h2u(h0), h2u(h1), h2u(h2), h2u(h3));
        }
    }
    // ---- scales: [row][block] -> sc[block][row] ----
    for (int idx = tid; idx < NTILE * 8; idx += THREADS) {
        const int r = idx >> 3, b = idx & 7;
        ((float*)(smem + SM_SC))[b * 64 + r] =
            __ldg(wscale + (size_t)(growbase + r) * (IN_F / 32) + ks * 8 + b);
    }

    float acc[4] = {0.f, 0.f, 0.f, 0.f};
    const int i  = lane & 7, jj = lane >> 3;
    const int am = i + ((jj & 1) << 3);                 // A fragment row (m)
    const int bn = (warp << 3) + (lane >> 2);           // B fragment row (n)
    const int n0 = (warp << 3) + ((lane & 3) << 1);     // D fragment n pair
    const u32 xt0 = sb + SM_XT;

#pragma unroll
    for (int c = 0; c < NCHUNK; c++) {
        asm volatile("cp.async.wait_group 1;\n" ::: "memory");   // stage c landed
        __syncthreads();                                         // publish to CTA

        // issue stage c+2 into the slot consumed at chunk c-1
        if (c + RING - 1 < NCHUNK) {
            const int p = c + RING - 1;
            const u32 d = wdst + (u32)((p % RING) * WSTAGE);
#pragma unroll
            for (int j = 0; j < 4; j++)
                cp16(d + j * 64, wsrc + p * KCHUNK + j * 16);
        }
        asm volatile("cp.async.commit_group;\n" ::: "memory");

        const u32 wst = sb + SM_W + (u32)((c % RING) * WSTAGE);
        float pd0[4], pd1[4];
#pragma unroll
        for (int s = 0; s < 4; s++) {
            // A fragment via ldmatrix
            const int au   = c * 8 + 2 * s + (jj >> 1);
            const u32 aoff = am * 512 + ((au ^ (am & 7)) << 4);
            u32 ah[4];
            ldsm4(ah, xt0 + aoff);
            // B fragment straight from raw nibbles (conflict-free stride 288)
            const u32 baddr = wst + bn * WSTRIDE + ((16 * s + 2 * (lane & 3)) << 2);
            const int2 q0 = *(const int2*)__cvta_shared_to_generic((size_t)baddr);
            const int2 q1 = *(const int2*)__cvta_shared_to_generic((size_t)(baddr + 32));
            const u32 b0 = qpair(q0.x, q0.y);
            const u32 b1 = qpair(q1.x, q1.y);
            float* pd = (s < 2) ? pd0 : pd1;
            if (s == 0 || s == 2) mma16816_z(pd, ah, b0, b1);
            else                  mma16816  (pd, ah, b0, b1);
        }
        // per-32k-block scales: blocks 2c (k 0-31) and 2c+1 (k 32-63)
        const float* scp = (const float*)(smem + SM_SC);
        const float2 sv0 = *(const float2*)(scp + (2 * c)     * 64 + n0);
        const float2 sv1 = *(const float2*)(scp + (2 * c + 1) * 64 + n0);
        acc[0] = fmaf(pd0[0], sv0.x, acc[0]); acc[0] = fmaf(pd1[0], sv1.x, acc[0]);
        acc[1] = fmaf(pd0[1], sv0.y, acc[1]); acc[1] = fmaf(pd1[1], sv1.y, acc[1]);
        acc[2] = fmaf(pd0[2], sv0.x, acc[2]); acc[2] = fmaf(pd1[2], sv1.x, acc[2]);
        acc[3] = fmaf(pd0[3], sv0.y, acc[3]); acc[3] = fmaf(pd1[3], sv1.y, acc[3]);
    }

    // ---- epilogue: accumulate directly into out (bias preloaded) ----
    const int m    = lane >> 2;
    const int grow = growbase + n0;
    atomicAdd(&out[(size_t)m * OUT_F + grow],           acc[0]);
    atomicAdd(&out[(size_t)m * OUT_F + grow + 1],       acc[1]);
    atomicAdd(&out[(size_t)(m + 8) * OUT_F + grow],     acc[2]);
    atomicAdd(&out[(size_t)(m + 8) * OUT_F + grow + 1], acc[3]);
}

extern "C" void kernel_launch(void* const* d_in, const int* in_sizes, int n_in,
                              void* d_out, int out_size) {
    const float* x      = (const float*)d_in[0];  // [16, 4096]
    const int*   wq     = (const int*)  d_in[1];  // [11008, 4096]
    const float* wscale = (const float*)d_in[2];  // [11008, 128]
    const float* bias   = (const float*)d_in[3];  // [11008]
    float* out = (float*)d_out;                   // [16, 11008]

    cudaFuncSetAttribute(q4_cp_kernel,
                         cudaFuncAttributeMaxDynamicSharedMemorySize, SM_TOTAL);
    bias_init_kernel<<<(TOK * OUT_F / 4) / 256, 256>>>(bias, out);
    q4_cp_kernel<<<dim3(NCTA_N, KSPLIT), THREADS, SM_TOTAL>>>(x, wq, wscale, out);
}

// round 17
// speedup vs baseline: 2.8337x; 1.0960x over previous
#include <cuda_runtime.h>
#include <cuda_fp16.h>
#include <cstdint>

typedef unsigned int u32;

#define IN_F    4096
#define OUT_F   11008
#define TOK     16
#define THREADS 256
#define NTILE   64
#define NCTA_N  (OUT_F / NTILE)     // 172
#define KSPLIT  8
#define KPER    (IN_F / KSPLIT)     // 512
#define KCHUNK  64
#define NCHUNK  (KPER / KCHUNK)     // 8
#define RING    3

// dynamic smem layout (bytes)
#define SM_XT    0                  // x tile: [16 m][64 units]*16B = 16384
#define SM_W     16384              // RING * 64 rows * 288B = 55296
#define SM_SC    71680              // [16 blk][64 row] f32 = 4096
#define SM_TOTAL 75776
#define WSTRIDE  288                // 72 words == 8 mod 32 -> conflict-free B LDS.64
#define WSTAGE   (64 * WSTRIDE)     // 18432

__device__ __forceinline__ u32 h2u(__half2 h) { return *reinterpret_cast<u32*>(&h); }
__device__ __forceinline__ __half2 u2h(u32 v) { return *reinterpret_cast<__half2*>(&v); }

__device__ __forceinline__ void mma16816(float* d, const u32* a, u32 b0, u32 b1) {
    asm volatile(
        "mma.sync.aligned.m16n8k16.row.col.f32.f16.f16.f32 "
        "{%0,%1,%2,%3}, {%4,%5,%6,%7}, {%8,%9}, {%0,%1,%2,%3};"
        : "+f"(d[0]), "+f"(d[1]), "+f"(d[2]), "+f"(d[3])
        : "r"(a[0]), "r"(a[1]), "r"(a[2]), "r"(a[3]), "r"(b0), "r"(b1));
}
__device__ __forceinline__ void mma16816_z(float* d, const u32* a, u32 b0, u32 b1) {
    asm volatile(
        "mma.sync.aligned.m16n8k16.row.col.f32.f16.f16.f32 "
        "{%0,%1,%2,%3}, {%4,%5,%6,%7}, {%8,%9}, {%10,%10,%10,%10};"
        : "=f"(d[0]), "=f"(d[1]), "=f"(d[2]), "=f"(d[3])
        : "r"(a[0]), "r"(a[1]), "r"(a[2]), "r"(a[3]), "r"(b0), "r"(b1), "f"(0.0f));
}
__device__ __forceinline__ void ldsm4(u32* r, u32 a) {
    asm volatile("ldmatrix.sync.aligned.m8n8.x4.shared.b16 {%0,%1,%2,%3}, [%4];"
                 : "=r"(r[0]), "=r"(r[1]), "=r"(r[2]), "=r"(r[3]) : "r"(a));
}
__device__ __forceinline__ void cp16(u32 dst, const void* src) {
    asm volatile("cp.async.cg.shared.global [%0], [%1], 16;\n" :: "r"(dst), "l"(src));
}

// raw nibble pair -> fp16 integers (q-8), exact: (0x6400|q) = 1024+q, minus 1032
__device__ __forceinline__ u32 qpair(int q0, int q1) {
    const u32 t = ((u32)q0 | ((u32)q1 << 16)) | 0x64006400u;
    return h2u(__hsub2(u2h(t), u2h(0x64086408u)));
}

// out[t][r] = bias[r] before the main kernel accumulates into it
__global__ void bias_init_kernel(const float* __restrict__ bias,
                                 float* __restrict__ out) {
    const int idx = blockIdx.x * 256 + threadIdx.x;   // 0..44031 float4s
    const int r4  = idx % (OUT_F / 4);
    ((float4*)out)[idx] = *(const float4*)&bias[r4 * 4];
}

__global__ void __launch_bounds__(THREADS, 3) q4_cp_kernel(
    const float* __restrict__ x,        // [16, 4096]
    const int*   __restrict__ wq,       // [11008, 4096]
    const float* __restrict__ wscale,   // [11008, 128]
    float*       __restrict__ out)      // [16, 11008], preloaded with bias
{
    extern __shared__ char smem[];
    const u32 sb = (u32)__cvta_generic_to_shared(smem);
    const int tid  = threadIdx.x;
    const int warp = tid >> 5;
    const int lane = tid & 31;
    const int growbase = blockIdx.x * NTILE;
    const int ks    = blockIdx.y;
    const int kbase = ks * KPER;

    // ---- w cp.async prologue FIRST: get DRAM moving before x conversion ----
    const int prow = tid >> 2;
    const int pcol = tid & 3;
    const int* wsrc = wq + (size_t)(growbase + prow) * IN_F + kbase + pcol * 4;
    const u32  wdst = sb + SM_W + prow * WSTRIDE + pcol * 16;

#pragma unroll
    for (int p = 0; p < RING - 1; p++) {    // stages 0,1
#pragma unroll
        for (int j = 0; j < 4; j++)
            cp16(wdst + p * WSTAGE + j * 64, wsrc + p * KCHUNK + j * 16);
        asm volatile("cp.async.commit_group;\n" ::: "memory");
    }

    // ---- convert this CTA's x k-range to fp16 tile (overlaps W stage DMAs) ----
    {
        const int m = tid >> 4;             // token
#pragma unroll
        for (int j = 0; j < 4; j++) {
            const int u = (tid & 15) + 16 * j;   // lane-contiguous 16B units
            const float4 v0 = *(const float4*)(x + (size_t)m * IN_F + kbase + u * 8);
            const float4 v1 = *(const float4*)(x + (size_t)m * IN_F + kbase + u * 8 + 4);
            const __half2 h0 = __floats2half2_rn(v0.x, v0.y);
            const __half2 h1 = __floats2half2_rn(v0.z, v0.w);
            const __half2 h2 = __floats2half2_rn(v1.x, v1.y);
            const __half2 h3 = __floats2half2_rn(v1.z, v1.w);
            const int up = u ^ (m & 7);     // ldmatrix-phase conflict-free swizzle
            *(uint4*)(smem + SM_XT + m * 1024 + up * 16) =
                make_uint4(h2u(h0), h2u(h1), h2u(h2), h2u(h3));
        }
    }
    // ---- scales: [row][block] -> sc[block][row] ----
#pragma unroll
    for (int idx = tid; idx < NTILE * 16; idx += THREADS) {
        const int r = idx >> 4, b = idx & 15;
        ((float*)(smem + SM_SC))[b * 64 + r] =
            __ldg(wscale + (size_t)(growbase + r) * (IN_F / 32) + ks * 16 + b);
    }

    float acc[4] = {0.f, 0.f, 0.f, 0.f};
    const int i  = lane & 7, jj = lane >> 3;
    const int am = i + ((jj & 1) << 3);                 // A fragment row (m)
    const int bn = (warp << 3) + (lane >> 2);           // B fragment row (n)
    const int n0 = (warp << 3) + ((lane & 3) << 1);     // D fragment n pair
    const u32 xt0 = sb + SM_XT;

#pragma unroll
    for (int c = 0; c < NCHUNK; c++) {
        asm volatile("cp.async.wait_group 1;\n" ::: "memory");   // stage c landed
        __syncthreads();                                         // publish to CTA

        // issue stage c+2 into the slot consumed at chunk c-1
        if (c + RING - 1 < NCHUNK) {
            const int p = c + RING - 1;
            const u32 d = wdst + (u32)((p % RING) * WSTAGE);
#pragma unroll
            for (int j = 0; j < 4; j++)
                cp16(d + j * 64, wsrc + p * KCHUNK + j * 16);
        }
        asm volatile("cp.async.commit_group;\n" ::: "memory");

        const u32 wst = sb + SM_W + (u32)((c % RING) * WSTAGE);
        float pd0[4], pd1[4];
#pragma unroll
        for (int s = 0; s < 4; s++) {
            // A fragment via ldmatrix
            const int au   = c * 8 + 2 * s + (jj >> 1);
            const u32 aoff = am * 1024 + ((au ^ (am & 7)) << 4);
            u32 ah[4];
            ldsm4(ah, xt0 + aoff);
            // B fragment straight from raw nibbles (conflict-free stride 288)
            const u32 baddr = wst + bn * WSTRIDE + ((16 * s + 2 * (lane & 3)) << 2);
            const int2 q0 = *(const int2*)__cvta_shared_to_generic((size_t)baddr);
            const int2 q1 = *(const int2*)__cvta_shared_to_generic((size_t)(baddr + 32));
            const u32 b0 = qpair(q0.x, q0.y);
            const u32 b1 = qpair(q1.x, q1.y);
            float* pd = (s < 2) ? pd0 : pd1;
            if (s == 0 || s == 2) mma16816_z(pd, ah, b0, b1);
            else                  mma16816  (pd, ah, b0, b1);
        }
        // per-32k-block scales: blocks 2c (k 0-31) and 2c+1 (k 32-63)
        const float* scp = (const float*)(smem + SM_SC);
        const float2 sv0 = *(const float2*)(scp + (2 * c)     * 64 + n0);
        const float2 sv1 = *(const float2*)(scp + (2 * c + 1) * 64 + n0);
        acc[0] = fmaf(pd0[0], sv0.x, acc[0]); acc[0] = fmaf(pd1[0], sv1.x, acc[0]);
        acc[1] = fmaf(pd0[1], sv0.y, acc[1]); acc[1] = fmaf(pd1[1], sv1.y, acc[1]);
        acc[2] = fmaf(pd0[2], sv0.x, acc[2]); acc[2] = fmaf(pd1[2], sv1.x, acc[2]);
        acc[3] = fmaf(pd0[3], sv0.y, acc[3]); acc[3] = fmaf(pd1[3], sv1.y, acc[3]);
    }

    // ---- epilogue: accumulate directly into out (bias preloaded) ----
    const int m    = lane >> 2;
    const int grow = growbase + n0;
    atomicAdd(&out[(size_t)m * OUT_F + grow],           acc[0]);
    atomicAdd(&out[(size_t)m * OUT_F + grow + 1],       acc[1]);
    atomicAdd(&out[(size_t)(m + 8) * OUT_F + grow],     acc[2]);
    atomicAdd(&out[(size_t)(m + 8) * OUT_F + grow + 1], acc[3]);
}

extern "C" void kernel_launch(void* const* d_in, const int* in_sizes, int n_in,
                              void* d_out, int out_size) {
    const float* x      = (const float*)d_in[0];  // [16, 4096]
    const int*   wq     = (const int*)  d_in[1];  // [11008, 4096]
    const float* wscale = (const float*)d_in[2];  // [11008, 128]
    const float* bias   = (const float*)d_in[3];  // [11008]
    float* out = (float*)d_out;                   // [16, 11008]

    cudaFuncSetAttribute(q4_cp_kernel,
                         cudaFuncAttributeMaxDynamicSharedMemorySize, SM_TOTAL);
    bias_init_kernel<<<(TOK * OUT_F / 4) / 256, 256>>>(bias, out);
    q4_cp_kernel<<<dim3(NCTA_N, KSPLIT), THREADS, SM_TOTAL>>>(x, wq, wscale, out);
}